// round 1
// baseline (speedup 1.0000x reference)
#include <cuda_runtime.h>
#include <math.h>

// Problem constants
#define NB     2048            // batch groups b
#define KOBJ   8               // K objects
#define H1     250
#define HA_N   100
#define MX     576
#define ROWS   (NB*KOBJ)       // 16384

// Scratch (device globals; no allocations allowed)
__device__ float g_s1 [ROWS*H1];
__device__ float g_P  [ROWS*H1];
__device__ float g_Q  [ROWS*H1];
__device__ float g_eff[ROWS*H1];

__device__ __forceinline__ float warp_sum(float v) {
#pragma unroll
    for (int o = 16; o; o >>= 1) v += __shfl_xor_sync(0xffffffffu, v, o);
    return v;
}

// ---------------------------------------------------------------------------
// Generic tiled SGEMM: C = epi(A[M,K] @ W[K,N]); BM=32, BN=256(>=N), BK=16.
// 256 threads: tx=lane (8 cols each), ty=warp (4 rows each).
// EPI==0: plain store. EPI==1: +bias, relu, LayerNorm(g,bt).
// ---------------------------------------------------------------------------
template <int EPI>
__global__ __launch_bounds__(256)
void gemm_kernel(const float* __restrict__ A, const float* __restrict__ W,
                 const float* __restrict__ bias, const float* __restrict__ g,
                 const float* __restrict__ bt, float* __restrict__ C,
                 int M, int K, int N)
{
    __shared__ float sA[32 * 17];
    __shared__ float sW[16 * 256];
    const int tid = threadIdx.x;
    const int tx = tid & 31, ty = tid >> 5;
    const int row0 = blockIdx.x * 32;

    float acc[4][8];
#pragma unroll
    for (int r = 0; r < 4; ++r)
#pragma unroll
        for (int c = 0; c < 8; ++c) acc[r][c] = 0.f;

    for (int kt = 0; kt < K; kt += 16) {
#pragma unroll
        for (int t = 0; t < 2; ++t) {
            int idx = tid + t * 256;
            int r = idx >> 4, kk = idx & 15;
            int k = kt + kk;
            sA[r * 17 + kk] = (k < K) ? A[(size_t)(row0 + r) * K + k] : 0.f;
        }
#pragma unroll
        for (int t = 0; t < 16; ++t) {
            int k = kt + t;
            sW[t * 256 + tid] = (k < K && tid < N) ? W[(size_t)k * N + tid] : 0.f;
        }
        __syncthreads();
#pragma unroll
        for (int kk = 0; kk < 16; ++kk) {
            float a[4];
#pragma unroll
            for (int rr = 0; rr < 4; ++rr) a[rr] = sA[(ty * 4 + rr) * 17 + kk];
            float4 w0 = *(const float4*)&sW[kk * 256 + tx * 8];
            float4 w1 = *(const float4*)&sW[kk * 256 + tx * 8 + 4];
            float w[8] = {w0.x, w0.y, w0.z, w0.w, w1.x, w1.y, w1.z, w1.w};
#pragma unroll
            for (int rr = 0; rr < 4; ++rr)
#pragma unroll
                for (int cc = 0; cc < 8; ++cc) acc[rr][cc] += a[rr] * w[cc];
        }
        __syncthreads();
    }

    if (EPI == 0) {
#pragma unroll
        for (int rr = 0; rr < 4; ++rr) {
            int row = row0 + ty * 4 + rr;
#pragma unroll
            for (int cc = 0; cc < 8; ++cc) {
                int n = tx * 8 + cc;
                if (n < N) C[(size_t)row * N + n] = acc[rr][cc];
            }
        }
    } else {
        float invN = 1.f / (float)N;
#pragma unroll
        for (int rr = 0; rr < 4; ++rr) {
            int row = row0 + ty * 4 + rr;
            float v[8]; float s = 0.f;
#pragma unroll
            for (int cc = 0; cc < 8; ++cc) {
                int n = tx * 8 + cc;
                float t = 0.f;
                if (n < N) t = fmaxf(acc[rr][cc] + bias[n], 0.f);
                v[cc] = t; s += t;
            }
            s = warp_sum(s);
            float mu = s * invN;
            float q = 0.f;
#pragma unroll
            for (int cc = 0; cc < 8; ++cc) {
                int n = tx * 8 + cc;
                if (n < N) { float d = v[cc] - mu; q += d * d; }
            }
            q = warp_sum(q);
            float rs = rsqrtf(q * invN + 1e-5f);
#pragma unroll
            for (int cc = 0; cc < 8; ++cc) {
                int n = tx * 8 + cc;
                if (n < N) C[(size_t)row * N + n] = (v[cc] - mu) * rs * g[n] + bt[n];
            }
        }
    }
}

// ---------------------------------------------------------------------------
// Output GEMM: new_state = [s1 | effect | x] @ out_W + out_b.
// A gathered from 3 sources; K = 1076, N = 250, M = 16384.
// ---------------------------------------------------------------------------
__global__ __launch_bounds__(256)
void out_gemm_kernel(const float* __restrict__ s1, const float* __restrict__ eff,
                     const float* __restrict__ x, const float* __restrict__ W,
                     const float* __restrict__ bias, float* __restrict__ C)
{
    const int K = 1076, N = 250;
    __shared__ float sA[32 * 17];
    __shared__ float sW[16 * 256];
    const int tid = threadIdx.x;
    const int tx = tid & 31, ty = tid >> 5;
    const int row0 = blockIdx.x * 32;

    float acc[4][8];
#pragma unroll
    for (int r = 0; r < 4; ++r)
#pragma unroll
        for (int c = 0; c < 8; ++c) acc[r][c] = 0.f;

    for (int kt = 0; kt < K; kt += 16) {
#pragma unroll
        for (int t = 0; t < 2; ++t) {
            int idx = tid + t * 256;
            int r = idx >> 4, kk = idx & 15;
            int k = kt + kk;
            int row = row0 + r;
            float av = 0.f;
            if (k < 250)       av = s1 [(size_t)row * 250 + k];
            else if (k < 500)  av = eff[(size_t)row * 250 + (k - 250)];
            else if (k < 1076) av = x  [(size_t)row * 576 + (k - 500)];
            sA[r * 17 + kk] = av;
        }
#pragma unroll
        for (int t = 0; t < 16; ++t) {
            int k = kt + t;
            sW[t * 256 + tid] = (k < K && tid < N) ? W[(size_t)k * N + tid] : 0.f;
        }
        __syncthreads();
#pragma unroll
        for (int kk = 0; kk < 16; ++kk) {
            float a[4];
#pragma unroll
            for (int rr = 0; rr < 4; ++rr) a[rr] = sA[(ty * 4 + rr) * 17 + kk];
            float4 w0 = *(const float4*)&sW[kk * 256 + tx * 8];
            float4 w1 = *(const float4*)&sW[kk * 256 + tx * 8 + 4];
            float w[8] = {w0.x, w0.y, w0.z, w0.w, w1.x, w1.y, w1.z, w1.w};
#pragma unroll
            for (int rr = 0; rr < 4; ++rr)
#pragma unroll
                for (int cc = 0; cc < 8; ++cc) acc[rr][cc] += a[rr] * w[cc];
        }
        __syncthreads();
    }
#pragma unroll
    for (int rr = 0; rr < 4; ++rr) {
        int row = row0 + ty * 4 + rr;
#pragma unroll
        for (int cc = 0; cc < 8; ++cc) {
            int n = tx * 8 + cc;
            if (n < N) C[(size_t)row * N + n] = acc[rr][cc] + bias[n];
        }
    }
}

// ---------------------------------------------------------------------------
// Fused pair kernel: one block per b (56 pair rows).
//  core_out = LN(relu(P[i] + Q[j] + core_b))       -> SMEM 56x250
//  att      = sigmoid(LN(tanh(core@attW1+b1))@attW2+b2)
//  ctx      = LN(relu(core@ctxW + ctx_b))
//  effect[b*8+i] = sum_jj ctx[i*7+jj] * att[i*7+jj]   (in-register reduce)
// Thread map: tx=lane (8 ctx cols / 4 att cols), ty=warp owns rows ty*7..ty*7+6
// (one i-group -> effect reduces locally, no atomics).
// ---------------------------------------------------------------------------
#define SM_P   0
#define SM_Q   (8 * 252)
#define SM_C   (2 * 8 * 252)          /* 4032  */
#define SM_W   (SM_C + 56 * 260)      /* 18592 */
#define SM_ATT (SM_W + 16 * 256)      /* 22688 */
#define SM_TOT (SM_ATT + 64)          /* 22752 floats = 91008 B */

__global__ __launch_bounds__(256, 2)
void pair_kernel(const float* __restrict__ P, const float* __restrict__ Q,
                 const float* __restrict__ core_b, const float* __restrict__ core_g,
                 const float* __restrict__ core_bt,
                 const float* __restrict__ ctxW, const float* __restrict__ ctx_b,
                 const float* __restrict__ ctx_g, const float* __restrict__ ctx_bt,
                 const float* __restrict__ attW1, const float* __restrict__ att_b1,
                 const float* __restrict__ att_g, const float* __restrict__ att_bt,
                 const float* __restrict__ attW2, const float* __restrict__ att_b2,
                 float* __restrict__ effect)
{
    extern __shared__ float sm[];
    float* sP   = sm + SM_P;
    float* sQ   = sm + SM_Q;
    float* sC   = sm + SM_C;
    float* sW   = sm + SM_W;
    float* sAtt = sm + SM_ATT;

    const int tid = threadIdx.x;
    const int tx = tid & 31, ty = tid >> 5;
    const int b = blockIdx.x;

    // --- load P,Q rows for this b ---
    for (int idx = tid; idx < 8 * 250; idx += 256) {
        int i = idx / 250, c = idx % 250;
        sP[i * 252 + c] = P[(size_t)(b * 8 + i) * 250 + c];
        sQ[i * 252 + c] = Q[(size_t)(b * 8 + i) * 250 + c];
    }
    __syncthreads();

    // --- core_out rows: relu(P[i]+Q[j]+b) then LN ---
    for (int r = ty; r < 56; r += 8) {
        int i = r / 7, jj = r % 7;
        int j = jj + (jj >= i ? 1 : 0);
        float v[8]; float s = 0.f;
#pragma unroll
        for (int t = 0; t < 8; ++t) {
            int c = tx + 32 * t;
            float val = 0.f;
            if (c < 250) val = fmaxf(sP[i * 252 + c] + sQ[j * 252 + c] + core_b[c], 0.f);
            v[t] = val; s += val;
        }
        s = warp_sum(s);
        float mu = s * (1.f / 250.f);
        float q = 0.f;
#pragma unroll
        for (int t = 0; t < 8; ++t) {
            int c = tx + 32 * t;
            if (c < 250) { float d = v[t] - mu; q += d * d; }
        }
        q = warp_sum(q);
        float rs = rsqrtf(q * (1.f / 250.f) + 1e-5f);
#pragma unroll
        for (int t = 0; t < 8; ++t) {
            int c = tx + 32 * t;
            if (c < 250)      sC[r * 260 + c] = (v[t] - mu) * rs * core_g[c] + core_bt[c];
            else if (c < 260) sC[r * 260 + c] = 0.f;   // zero pad (read by GEMM tail)
        }
    }
    __syncthreads();

    // --- attention GEMM: 56 x 100, K=250 ---
    float accA[7][4];
#pragma unroll
    for (int r = 0; r < 7; ++r)
#pragma unroll
        for (int c = 0; c < 4; ++c) accA[r][c] = 0.f;

    for (int kt = 0; kt < 250; kt += 16) {
#pragma unroll
        for (int t = 0; t < 8; ++t) {
            int idx = tid + t * 256;
            int kk = idx >> 7, n = idx & 127;
            int k = kt + kk;
            sW[kk * 256 + n] = (k < 250 && n < 100) ? attW1[(size_t)k * 100 + n] : 0.f;
        }
        __syncthreads();
#pragma unroll
        for (int kk = 0; kk < 16; ++kk) {
            float a[7];
#pragma unroll
            for (int rr = 0; rr < 7; ++rr) a[rr] = sC[(ty * 7 + rr) * 260 + kt + kk];
            float4 w4 = *(const float4*)&sW[kk * 256 + tx * 4];
            float w[4] = {w4.x, w4.y, w4.z, w4.w};
#pragma unroll
            for (int rr = 0; rr < 7; ++rr)
#pragma unroll
                for (int cc = 0; cc < 4; ++cc) accA[rr][cc] += a[rr] * w[cc];
        }
        __syncthreads();
    }

    // --- attention epilogue: tanh, LN(100), dot attW2, sigmoid ---
#pragma unroll
    for (int rr = 0; rr < 7; ++rr) {
        int row = ty * 7 + rr;
        float h[4]; float s = 0.f;
#pragma unroll
        for (int cc = 0; cc < 4; ++cc) {
            int c = tx * 4 + cc;
            float t = 0.f;
            if (c < 100) t = tanhf(accA[rr][cc] + att_b1[c]);
            h[cc] = t; s += t;
        }
        s = warp_sum(s);
        float mu = s * (1.f / 100.f);
        float q = 0.f;
#pragma unroll
        for (int cc = 0; cc < 4; ++cc) {
            int c = tx * 4 + cc;
            if (c < 100) { float d = h[cc] - mu; q += d * d; }
        }
        q = warp_sum(q);
        float rs = rsqrtf(q * (1.f / 100.f) + 1e-5f);
        float p = 0.f;
#pragma unroll
        for (int cc = 0; cc < 4; ++cc) {
            int c = tx * 4 + cc;
            if (c < 100) p += ((h[cc] - mu) * rs * att_g[c] + att_bt[c]) * attW2[c];
        }
        p = warp_sum(p);
        if (tx == 0) sAtt[row] = 1.f / (1.f + expf(-(p + att_b2[0])));
    }
    __syncthreads();

    // --- ctx GEMM: 56 x 250, K=250 ---
    float accC[7][8];
#pragma unroll
    for (int r = 0; r < 7; ++r)
#pragma unroll
        for (int c = 0; c < 8; ++c) accC[r][c] = 0.f;

    for (int kt = 0; kt < 250; kt += 16) {
#pragma unroll
        for (int t = 0; t < 16; ++t) {
            int k = kt + t;
            sW[t * 256 + tid] = (k < 250 && tid < 250) ? ctxW[(size_t)k * 250 + tid] : 0.f;
        }
        __syncthreads();
#pragma unroll
        for (int kk = 0; kk < 16; ++kk) {
            float a[7];
#pragma unroll
            for (int rr = 0; rr < 7; ++rr) a[rr] = sC[(ty * 7 + rr) * 260 + kt + kk];
            float4 w0 = *(const float4*)&sW[kk * 256 + tx * 8];
            float4 w1 = *(const float4*)&sW[kk * 256 + tx * 8 + 4];
            float w[8] = {w0.x, w0.y, w0.z, w0.w, w1.x, w1.y, w1.z, w1.w};
#pragma unroll
            for (int rr = 0; rr < 7; ++rr)
#pragma unroll
                for (int cc = 0; cc < 8; ++cc) accC[rr][cc] += a[rr] * w[cc];
        }
        __syncthreads();
    }

    // --- ctx epilogue + effect reduce (rows ty*7..ty*7+6 == i-group ty) ---
    float eff[8];
#pragma unroll
    for (int cc = 0; cc < 8; ++cc) eff[cc] = 0.f;
#pragma unroll
    for (int rr = 0; rr < 7; ++rr) {
        int row = ty * 7 + rr;
        float v[8]; float s = 0.f;
#pragma unroll
        for (int cc = 0; cc < 8; ++cc) {
            int c = tx * 8 + cc;
            float t = 0.f;
            if (c < 250) t = fmaxf(accC[rr][cc] + ctx_b[c], 0.f);
            v[cc] = t; s += t;
        }
        s = warp_sum(s);
        float mu = s * (1.f / 250.f);
        float q = 0.f;
#pragma unroll
        for (int cc = 0; cc < 8; ++cc) {
            int c = tx * 8 + cc;
            if (c < 250) { float d = v[cc] - mu; q += d * d; }
        }
        q = warp_sum(q);
        float rs = rsqrtf(q * (1.f / 250.f) + 1e-5f);
        float aw = sAtt[row];
#pragma unroll
        for (int cc = 0; cc < 8; ++cc) {
            int c = tx * 8 + cc;
            if (c < 250) eff[cc] += ((v[cc] - mu) * rs * ctx_g[c] + ctx_bt[c]) * aw;
        }
    }
#pragma unroll
    for (int cc = 0; cc < 8; ++cc) {
        int c = tx * 8 + cc;
        if (c < 250) effect[(size_t)(b * 8 + ty) * 250 + c] = eff[cc];
    }
}

// ---------------------------------------------------------------------------
extern "C" void kernel_launch(void* const* d_in, const int* in_sizes, int n_in,
                              void* d_out, int out_size)
{
    const float* x      = (const float*)d_in[0];
    const float* state  = (const float*)d_in[1];
    const float* enc_W  = (const float*)d_in[2];
    const float* enc_b  = (const float*)d_in[3];
    const float* enc_g  = (const float*)d_in[4];
    const float* enc_bt = (const float*)d_in[5];
    const float* core_W = (const float*)d_in[6];
    const float* core_b = (const float*)d_in[7];
    const float* core_g = (const float*)d_in[8];
    const float* core_bt= (const float*)d_in[9];
    const float* ctx_W  = (const float*)d_in[10];
    const float* ctx_b  = (const float*)d_in[11];
    const float* ctx_g  = (const float*)d_in[12];
    const float* ctx_bt = (const float*)d_in[13];
    const float* att_W1 = (const float*)d_in[14];
    const float* att_b1 = (const float*)d_in[15];
    const float* att_g  = (const float*)d_in[16];
    const float* att_bt = (const float*)d_in[17];
    const float* att_W2 = (const float*)d_in[18];
    const float* att_b2 = (const float*)d_in[19];
    const float* out_W  = (const float*)d_in[20];
    const float* out_b  = (const float*)d_in[21];
    float* out = (float*)d_out;

    float *p_s1, *p_P, *p_Q, *p_eff;
    cudaGetSymbolAddress((void**)&p_s1,  g_s1);
    cudaGetSymbolAddress((void**)&p_P,   g_P);
    cudaGetSymbolAddress((void**)&p_Q,   g_Q);
    cudaGetSymbolAddress((void**)&p_eff, g_eff);

    cudaFuncSetAttribute(pair_kernel, cudaFuncAttributeMaxDynamicSharedMemorySize,
                         SM_TOT * (int)sizeof(float));

    // 1) s1 = LN(relu(state @ enc_W + enc_b))
    gemm_kernel<1><<<ROWS / 32, 256>>>(state, enc_W, enc_b, enc_g, enc_bt,
                                       p_s1, ROWS, 250, 250);
    // 2) P = s1 @ core_W[:250], Q = s1 @ core_W[250:]
    gemm_kernel<0><<<ROWS / 32, 256>>>(p_s1, core_W, nullptr, nullptr, nullptr,
                                       p_P, ROWS, 250, 250);
    gemm_kernel<0><<<ROWS / 32, 256>>>(p_s1, core_W + 250 * 250, nullptr, nullptr, nullptr,
                                       p_Q, ROWS, 250, 250);
    // 3) fused pair/ctx/att/effect
    pair_kernel<<<NB, 256, SM_TOT * (int)sizeof(float)>>>(
        p_P, p_Q, core_b, core_g, core_bt,
        ctx_W, ctx_b, ctx_g, ctx_bt,
        att_W1, att_b1, att_g, att_bt,
        att_W2, att_b2, p_eff);
    // 4) new_state = [s1|effect|x] @ out_W + out_b
    out_gemm_kernel<<<ROWS / 32, 256>>>(p_s1, p_eff, x, out_W, out_b, out);
}

// round 2
// speedup vs baseline: 1.2223x; 1.2223x over previous
#include <cuda_runtime.h>
#include <math.h>

// Problem constants
#define NB     2048            // batch groups b
#define KOBJ   8               // K objects
#define H1     250
#define ROWS   (NB*KOBJ)       // 16384

// Scratch (device globals; no allocations allowed)
__device__ float g_s1 [ROWS*H1];
__device__ float g_P  [ROWS*H1];
__device__ float g_Q  [ROWS*H1];
__device__ float g_eff[ROWS*H1];

__device__ __forceinline__ float warp_sum(float v) {
#pragma unroll
    for (int o = 16; o; o >>= 1) v += __shfl_xor_sync(0xffffffffu, v, o);
    return v;
}

// ---------------------------------------------------------------------------
// Tiled SGEMM: C = epi(A[M,K] @ W[K,N]); BM=64, BN=256(>=N), BK=16.
// 256 threads: tx=lane (8 cols), ty=warp (8 rows). float4 kk-vectorized
// A-operand reads (sA row stride 20 keeps kk4*4 16B-aligned).
// EPI==0: plain store. EPI==1: +bias, relu, LayerNorm(g,bt).
// ---------------------------------------------------------------------------
template <int EPI>
__global__ __launch_bounds__(256, 2)
void gemm_kernel(const float* __restrict__ A, const float* __restrict__ W,
                 const float* __restrict__ bias, const float* __restrict__ g,
                 const float* __restrict__ bt, float* __restrict__ C,
                 int M, int K, int N)
{
    __shared__ float sA[64 * 20];
    __shared__ float sW[16 * 256];
    const int tid = threadIdx.x;
    const int tx = tid & 31, ty = tid >> 5;
    const int row0 = blockIdx.x * 64;

    float acc[8][8];
#pragma unroll
    for (int r = 0; r < 8; ++r)
#pragma unroll
        for (int c = 0; c < 8; ++c) acc[r][c] = 0.f;

    for (int kt = 0; kt < K; kt += 16) {
#pragma unroll
        for (int t = 0; t < 4; ++t) {
            int idx = tid + t * 256;
            int r = idx >> 4, kk = idx & 15;
            int k = kt + kk;
            sA[r * 20 + kk] = (k < K) ? A[(size_t)(row0 + r) * K + k] : 0.f;
        }
#pragma unroll
        for (int t = 0; t < 16; ++t) {
            int k = kt + t;
            sW[t * 256 + tid] = (k < K && tid < N) ? W[(size_t)k * N + tid] : 0.f;
        }
        __syncthreads();
#pragma unroll
        for (int k4 = 0; k4 < 4; ++k4) {
            float4 a4[8];
#pragma unroll
            for (int rr = 0; rr < 8; ++rr)
                a4[rr] = *(const float4*)&sA[(ty * 8 + rr) * 20 + k4 * 4];
#pragma unroll
            for (int m = 0; m < 4; ++m) {
                int kk = k4 * 4 + m;
                float4 w0 = *(const float4*)&sW[kk * 256 + tx * 8];
                float4 w1 = *(const float4*)&sW[kk * 256 + tx * 8 + 4];
                float w[8] = {w0.x, w0.y, w0.z, w0.w, w1.x, w1.y, w1.z, w1.w};
#pragma unroll
                for (int rr = 0; rr < 8; ++rr) {
                    float a = (m == 0) ? a4[rr].x : (m == 1) ? a4[rr].y
                             : (m == 2) ? a4[rr].z : a4[rr].w;
#pragma unroll
                    for (int cc = 0; cc < 8; ++cc) acc[rr][cc] += a * w[cc];
                }
            }
        }
        __syncthreads();
    }

    if (EPI == 0) {
#pragma unroll
        for (int rr = 0; rr < 8; ++rr) {
            int row = row0 + ty * 8 + rr;
#pragma unroll
            for (int cc = 0; cc < 8; ++cc) {
                int n = tx * 8 + cc;
                if (n < N) C[(size_t)row * N + n] = acc[rr][cc];
            }
        }
    } else {
        float invN = 1.f / (float)N;
#pragma unroll
        for (int rr = 0; rr < 8; ++rr) {
            int row = row0 + ty * 8 + rr;
            float v[8]; float s = 0.f;
#pragma unroll
            for (int cc = 0; cc < 8; ++cc) {
                int n = tx * 8 + cc;
                float t = 0.f;
                if (n < N) t = fmaxf(acc[rr][cc] + bias[n], 0.f);
                v[cc] = t; s += t;
            }
            s = warp_sum(s);
            float mu = s * invN;
            float q = 0.f;
#pragma unroll
            for (int cc = 0; cc < 8; ++cc) {
                int n = tx * 8 + cc;
                if (n < N) { float d = v[cc] - mu; q += d * d; }
            }
            q = warp_sum(q);
            float rs = rsqrtf(q * invN + 1e-5f);
#pragma unroll
            for (int cc = 0; cc < 8; ++cc) {
                int n = tx * 8 + cc;
                if (n < N) C[(size_t)row * N + n] = (v[cc] - mu) * rs * g[n] + bt[n];
            }
        }
    }
}

// ---------------------------------------------------------------------------
// Output GEMM: new_state = [s1 | effect | x] @ out_W + out_b.
// K = 1076, N = 250, M = 16384. Same BM=64 tile as gemm_kernel.
// ---------------------------------------------------------------------------
__global__ __launch_bounds__(256, 2)
void out_gemm_kernel(const float* __restrict__ s1, const float* __restrict__ eff,
                     const float* __restrict__ x, const float* __restrict__ W,
                     const float* __restrict__ bias, float* __restrict__ C)
{
    const int K = 1076, N = 250;
    __shared__ float sA[64 * 20];
    __shared__ float sW[16 * 256];
    const int tid = threadIdx.x;
    const int tx = tid & 31, ty = tid >> 5;
    const int row0 = blockIdx.x * 64;

    float acc[8][8];
#pragma unroll
    for (int r = 0; r < 8; ++r)
#pragma unroll
        for (int c = 0; c < 8; ++c) acc[r][c] = 0.f;

    for (int kt = 0; kt < K; kt += 16) {
#pragma unroll
        for (int t = 0; t < 4; ++t) {
            int idx = tid + t * 256;
            int r = idx >> 4, kk = idx & 15;
            int k = kt + kk;
            int row = row0 + r;
            float av = 0.f;
            if (k < 250)       av = s1 [(size_t)row * 250 + k];
            else if (k < 500)  av = eff[(size_t)row * 250 + (k - 250)];
            else if (k < 1076) av = x  [(size_t)row * 576 + (k - 500)];
            sA[r * 20 + kk] = av;
        }
#pragma unroll
        for (int t = 0; t < 16; ++t) {
            int k = kt + t;
            sW[t * 256 + tid] = (k < K && tid < N) ? W[(size_t)k * N + tid] : 0.f;
        }
        __syncthreads();
#pragma unroll
        for (int k4 = 0; k4 < 4; ++k4) {
            float4 a4[8];
#pragma unroll
            for (int rr = 0; rr < 8; ++rr)
                a4[rr] = *(const float4*)&sA[(ty * 8 + rr) * 20 + k4 * 4];
#pragma unroll
            for (int m = 0; m < 4; ++m) {
                int kk = k4 * 4 + m;
                float4 w0 = *(const float4*)&sW[kk * 256 + tx * 8];
                float4 w1 = *(const float4*)&sW[kk * 256 + tx * 8 + 4];
                float w[8] = {w0.x, w0.y, w0.z, w0.w, w1.x, w1.y, w1.z, w1.w};
#pragma unroll
                for (int rr = 0; rr < 8; ++rr) {
                    float a = (m == 0) ? a4[rr].x : (m == 1) ? a4[rr].y
                             : (m == 2) ? a4[rr].z : a4[rr].w;
#pragma unroll
                    for (int cc = 0; cc < 8; ++cc) acc[rr][cc] += a * w[cc];
                }
            }
        }
        __syncthreads();
    }
#pragma unroll
    for (int rr = 0; rr < 8; ++rr) {
        int row = row0 + ty * 8 + rr;
#pragma unroll
        for (int cc = 0; cc < 8; ++cc) {
            int n = tx * 8 + cc;
            if (n < N) C[(size_t)row * N + n] = acc[rr][cc] + bias[n];
        }
    }
}

// ---------------------------------------------------------------------------
// Fused pair kernel: one block per b (56 pair rows).
//  core_out = LN(relu(P[i] + Q[j] + core_b))       -> SMEM 56x256 (zero-pad)
//  att      = sigmoid(LN(tanh(core@attW1+b1))@attW2+b2)
//  ctx      = LN(relu(core@ctxW + ctx_b))
//  effect[b*8+i] = sum_jj ctx[i*7+jj]*att[i*7+jj]  (in-register, no atomics)
// SMEM: sC 56x256 | union{ sP/sQ staging , weight tile 16x256 } | sAtt.
// A-operand reads vectorized (float4 over kk; sC stride 256, kt mult of 16).
// ---------------------------------------------------------------------------
#define SC_STRIDE 256
#define SM_SC   0
#define SM_UN   (56 * SC_STRIDE)        /* 14336: union region, 4096 floats */
#define SM_ATT  (SM_UN + 4096)          /* 18432 */
#define SM_TOT  (SM_ATT + 64)           /* 18496 floats = 73984 B */

__global__ __launch_bounds__(256, 2)
void pair_kernel(const float* __restrict__ P, const float* __restrict__ Q,
                 const float* __restrict__ core_b, const float* __restrict__ core_g,
                 const float* __restrict__ core_bt,
                 const float* __restrict__ ctxW, const float* __restrict__ ctx_b,
                 const float* __restrict__ ctx_g, const float* __restrict__ ctx_bt,
                 const float* __restrict__ attW1, const float* __restrict__ att_b1,
                 const float* __restrict__ att_g, const float* __restrict__ att_bt,
                 const float* __restrict__ attW2, const float* __restrict__ att_b2,
                 float* __restrict__ effect)
{
    extern __shared__ float sm[];
    float* sC   = sm + SM_SC;
    float* sP   = sm + SM_UN;            // staging (phase 1 only)
    float* sQ   = sm + SM_UN + 2016;     // 8*252
    float* sW   = sm + SM_UN;            // weight tiles (phases 2-3)
    float* sAtt = sm + SM_ATT;

    const int tid = threadIdx.x;
    const int tx = tid & 31, ty = tid >> 5;
    const int b = blockIdx.x;

    // --- phase 1: load P,Q rows, build core_out into sC ---
    for (int idx = tid; idx < 8 * 250; idx += 256) {
        int i = idx / 250, c = idx % 250;
        sP[i * 252 + c] = P[(size_t)(b * 8 + i) * 250 + c];
        sQ[i * 252 + c] = Q[(size_t)(b * 8 + i) * 250 + c];
    }
    __syncthreads();

    for (int r = ty; r < 56; r += 8) {
        int i = r / 7, jj = r % 7;
        int j = jj + (jj >= i ? 1 : 0);
        float v[8]; float s = 0.f;
#pragma unroll
        for (int t = 0; t < 8; ++t) {
            int c = tx + 32 * t;
            float val = 0.f;
            if (c < 250) val = fmaxf(sP[i * 252 + c] + sQ[j * 252 + c] + core_b[c], 0.f);
            v[t] = val; s += val;
        }
        s = warp_sum(s);
        float mu = s * (1.f / 250.f);
        float q = 0.f;
#pragma unroll
        for (int t = 0; t < 8; ++t) {
            int c = tx + 32 * t;
            if (c < 250) { float d = v[t] - mu; q += d * d; }
        }
        q = warp_sum(q);
        float rs = rsqrtf(q * (1.f / 250.f) + 1e-5f);
#pragma unroll
        for (int t = 0; t < 8; ++t) {
            int c = tx + 32 * t;
            if (c < 250) sC[r * SC_STRIDE + c] = (v[t] - mu) * rs * core_g[c] + core_bt[c];
            else         sC[r * SC_STRIDE + c] = 0.f;   // zero pad to 256
        }
    }
    __syncthreads();   // sP/sQ dead from here; sW may overwrite

    // --- phase 2: attention GEMM 56 x 100, K=250 (sW stride 128) ---
    float accA[7][4];
#pragma unroll
    for (int r = 0; r < 7; ++r)
#pragma unroll
        for (int c = 0; c < 4; ++c) accA[r][c] = 0.f;

    for (int kt = 0; kt < 250; kt += 16) {
#pragma unroll
        for (int t = 0; t < 8; ++t) {
            int idx = tid + t * 256;
            int kk = idx >> 7, n = idx & 127;
            int k = kt + kk;
            sW[kk * 128 + n] = (k < 250 && n < 100) ? attW1[(size_t)k * 100 + n] : 0.f;
        }
        __syncthreads();
#pragma unroll
        for (int k4 = 0; k4 < 4; ++k4) {
            float4 a4[7];
#pragma unroll
            for (int rr = 0; rr < 7; ++rr)
                a4[rr] = *(const float4*)&sC[(ty * 7 + rr) * SC_STRIDE + kt + k4 * 4];
#pragma unroll
            for (int m = 0; m < 4; ++m) {
                int kk = k4 * 4 + m;
                float4 w4 = *(const float4*)&sW[kk * 128 + tx * 4];
                float w[4] = {w4.x, w4.y, w4.z, w4.w};
#pragma unroll
                for (int rr = 0; rr < 7; ++rr) {
                    float a = (m == 0) ? a4[rr].x : (m == 1) ? a4[rr].y
                             : (m == 2) ? a4[rr].z : a4[rr].w;
#pragma unroll
                    for (int cc = 0; cc < 4; ++cc) accA[rr][cc] += a * w[cc];
                }
            }
        }
        __syncthreads();
    }

    // attention epilogue: tanh, LN(100), dot attW2, sigmoid
#pragma unroll
    for (int rr = 0; rr < 7; ++rr) {
        int row = ty * 7 + rr;
        float h[4]; float s = 0.f;
#pragma unroll
        for (int cc = 0; cc < 4; ++cc) {
            int c = tx * 4 + cc;
            float t = 0.f;
            if (c < 100) t = tanhf(accA[rr][cc] + att_b1[c]);
            h[cc] = t; s += t;
        }
        s = warp_sum(s);
        float mu = s * (1.f / 100.f);
        float q = 0.f;
#pragma unroll
        for (int cc = 0; cc < 4; ++cc) {
            int c = tx * 4 + cc;
            if (c < 100) { float d = h[cc] - mu; q += d * d; }
        }
        q = warp_sum(q);
        float rs = rsqrtf(q * (1.f / 100.f) + 1e-5f);
        float p = 0.f;
#pragma unroll
        for (int cc = 0; cc < 4; ++cc) {
            int c = tx * 4 + cc;
            if (c < 100) p += ((h[cc] - mu) * rs * att_g[c] + att_bt[c]) * attW2[c];
        }
        p = warp_sum(p);
        if (tx == 0) sAtt[row] = 1.f / (1.f + expf(-(p + att_b2[0])));
    }
    __syncthreads();

    // --- phase 3: ctx GEMM 56 x 250, K=250 (sW stride 256) ---
    float accC[7][8];
#pragma unroll
    for (int r = 0; r < 7; ++r)
#pragma unroll
        for (int c = 0; c < 8; ++c) accC[r][c] = 0.f;

    for (int kt = 0; kt < 250; kt += 16) {
#pragma unroll
        for (int t = 0; t < 16; ++t) {
            int k = kt + t;
            sW[t * 256 + tid] = (k < 250 && tid < 250) ? ctxW[(size_t)k * 250 + tid] : 0.f;
        }
        __syncthreads();
#pragma unroll
        for (int k4 = 0; k4 < 4; ++k4) {
            float4 a4[7];
#pragma unroll
            for (int rr = 0; rr < 7; ++rr)
                a4[rr] = *(const float4*)&sC[(ty * 7 + rr) * SC_STRIDE + kt + k4 * 4];
#pragma unroll
            for (int m = 0; m < 4; ++m) {
                int kk = k4 * 4 + m;
                float4 w0 = *(const float4*)&sW[kk * 256 + tx * 8];
                float4 w1 = *(const float4*)&sW[kk * 256 + tx * 8 + 4];
                float w[8] = {w0.x, w0.y, w0.z, w0.w, w1.x, w1.y, w1.z, w1.w};
#pragma unroll
                for (int rr = 0; rr < 7; ++rr) {
                    float a = (m == 0) ? a4[rr].x : (m == 1) ? a4[rr].y
                             : (m == 2) ? a4[rr].z : a4[rr].w;
#pragma unroll
                    for (int cc = 0; cc < 8; ++cc) accC[rr][cc] += a * w[cc];
                }
            }
        }
        __syncthreads();
    }

    // --- ctx epilogue + effect reduce (warp ty owns i-group ty) ---
    float eff[8];
#pragma unroll
    for (int cc = 0; cc < 8; ++cc) eff[cc] = 0.f;
#pragma unroll
    for (int rr = 0; rr < 7; ++rr) {
        int row = ty * 7 + rr;
        float v[8]; float s = 0.f;
#pragma unroll
        for (int cc = 0; cc < 8; ++cc) {
            int c = tx * 8 + cc;
            float t = 0.f;
            if (c < 250) t = fmaxf(accC[rr][cc] + ctx_b[c], 0.f);
            v[cc] = t; s += t;
        }
        s = warp_sum(s);
        float mu = s * (1.f / 250.f);
        float q = 0.f;
#pragma unroll
        for (int cc = 0; cc < 8; ++cc) {
            int c = tx * 8 + cc;
            if (c < 250) { float d = v[cc] - mu; q += d * d; }
        }
        q = warp_sum(q);
        float rs = rsqrtf(q * (1.f / 250.f) + 1e-5f);
        float aw = sAtt[row];
#pragma unroll
        for (int cc = 0; cc < 8; ++cc) {
            int c = tx * 8 + cc;
            if (c < 250) eff[cc] += ((v[cc] - mu) * rs * ctx_g[c] + ctx_bt[c]) * aw;
        }
    }
#pragma unroll
    for (int cc = 0; cc < 8; ++cc) {
        int c = tx * 8 + cc;
        if (c < 250) effect[(size_t)(b * 8 + ty) * 250 + c] = eff[cc];
    }
}

// ---------------------------------------------------------------------------
extern "C" void kernel_launch(void* const* d_in, const int* in_sizes, int n_in,
                              void* d_out, int out_size)
{
    const float* x      = (const float*)d_in[0];
    const float* state  = (const float*)d_in[1];
    const float* enc_W  = (const float*)d_in[2];
    const float* enc_b  = (const float*)d_in[3];
    const float* enc_g  = (const float*)d_in[4];
    const float* enc_bt = (const float*)d_in[5];
    const float* core_W = (const float*)d_in[6];
    const float* core_b = (const float*)d_in[7];
    const float* core_g = (const float*)d_in[8];
    const float* core_bt= (const float*)d_in[9];
    const float* ctx_W  = (const float*)d_in[10];
    const float* ctx_b  = (const float*)d_in[11];
    const float* ctx_g  = (const float*)d_in[12];
    const float* ctx_bt = (const float*)d_in[13];
    const float* att_W1 = (const float*)d_in[14];
    const float* att_b1 = (const float*)d_in[15];
    const float* att_g  = (const float*)d_in[16];
    const float* att_bt = (const float*)d_in[17];
    const float* att_W2 = (const float*)d_in[18];
    const float* att_b2 = (const float*)d_in[19];
    const float* out_W  = (const float*)d_in[20];
    const float* out_b  = (const float*)d_in[21];
    float* out = (float*)d_out;

    float *p_s1, *p_P, *p_Q, *p_eff;
    cudaGetSymbolAddress((void**)&p_s1,  g_s1);
    cudaGetSymbolAddress((void**)&p_P,   g_P);
    cudaGetSymbolAddress((void**)&p_Q,   g_Q);
    cudaGetSymbolAddress((void**)&p_eff, g_eff);

    cudaFuncSetAttribute(pair_kernel, cudaFuncAttributeMaxDynamicSharedMemorySize,
                         SM_TOT * (int)sizeof(float));

    // 1) s1 = LN(relu(state @ enc_W + enc_b))
    gemm_kernel<1><<<ROWS / 64, 256>>>(state, enc_W, enc_b, enc_g, enc_bt,
                                       p_s1, ROWS, 250, 250);
    // 2) P = s1 @ core_W[:250], Q = s1 @ core_W[250:]
    gemm_kernel<0><<<ROWS / 64, 256>>>(p_s1, core_W, nullptr, nullptr, nullptr,
                                       p_P, ROWS, 250, 250);
    gemm_kernel<0><<<ROWS / 64, 256>>>(p_s1, core_W + 250 * 250, nullptr, nullptr, nullptr,
                                       p_Q, ROWS, 250, 250);
    // 3) fused pair/ctx/att/effect
    pair_kernel<<<NB, 256, SM_TOT * (int)sizeof(float)>>>(
        p_P, p_Q, core_b, core_g, core_bt,
        ctx_W, ctx_b, ctx_g, ctx_bt,
        att_W1, att_b1, att_g, att_bt,
        att_W2, att_b2, p_eff);
    // 4) new_state = [s1|effect|x] @ out_W + out_b
    out_gemm_kernel<<<ROWS / 64, 256>>>(p_s1, p_eff, x, out_W, out_b, out);
}

// round 3
// speedup vs baseline: 1.3419x; 1.0979x over previous
#include <cuda_runtime.h>
#include <math.h>

// Problem constants
#define NB     2048            // batch groups b
#define KOBJ   8               // K objects
#define H1     250
#define ROWS   (NB*KOBJ)       // 16384

// Scratch (device globals; no allocations allowed)
__device__ float g_s1 [ROWS*H1];
__device__ float g_P  [ROWS*H1];
__device__ float g_Q  [ROWS*H1];
__device__ float g_eff[ROWS*H1];

__device__ __forceinline__ float warp_sum(float v) {
#pragma unroll
    for (int o = 16; o; o >>= 1) v += __shfl_xor_sync(0xffffffffu, v, o);
    return v;
}

// Column owned by lane tx, slot cc under the conflict-free mapping:
// cc 0..3 -> tx*4+cc ; cc 4..7 -> 128 + tx*4 + (cc-4)
__device__ __forceinline__ int colmap(int tx, int cc) {
    return (cc < 4) ? (tx * 4 + cc) : (128 + tx * 4 + (cc - 4));
}

// ---------------------------------------------------------------------------
// Tiled SGEMM: C = epi(A[M,K] @ W[K,N]); BM=64, BN=256(>=N), BK=16.
// 256 threads: tx=lane (8 cols via colmap), ty=warp (8 rows).
// W reads: two contiguous LDS.128 slabs (tx*4 and 128+tx*4) -> conflict-free.
// EPI==0: plain store. EPI==1: +bias, relu, LayerNorm(g,bt).
// ---------------------------------------------------------------------------
template <int EPI>
__global__ __launch_bounds__(256, 2)
void gemm_kernel(const float* __restrict__ A, const float* __restrict__ W,
                 const float* __restrict__ bias, const float* __restrict__ g,
                 const float* __restrict__ bt, float* __restrict__ C,
                 int M, int K, int N)
{
    __shared__ float sA[64 * 20];
    __shared__ float sW[16 * 256];
    const int tid = threadIdx.x;
    const int tx = tid & 31, ty = tid >> 5;
    const int row0 = blockIdx.x * 64;

    float acc[8][8];
#pragma unroll
    for (int r = 0; r < 8; ++r)
#pragma unroll
        for (int c = 0; c < 8; ++c) acc[r][c] = 0.f;

    for (int kt = 0; kt < K; kt += 16) {
#pragma unroll
        for (int t = 0; t < 4; ++t) {
            int idx = tid + t * 256;
            int r = idx >> 4, kk = idx & 15;
            int k = kt + kk;
            sA[r * 20 + kk] = (k < K) ? A[(size_t)(row0 + r) * K + k] : 0.f;
        }
#pragma unroll
        for (int t = 0; t < 16; ++t) {
            int k = kt + t;
            sW[t * 256 + tid] = (k < K && tid < N) ? W[(size_t)k * N + tid] : 0.f;
        }
        __syncthreads();
#pragma unroll
        for (int k4 = 0; k4 < 4; ++k4) {
            float4 a4[8];
#pragma unroll
            for (int rr = 0; rr < 8; ++rr)
                a4[rr] = *(const float4*)&sA[(ty * 8 + rr) * 20 + k4 * 4];
#pragma unroll
            for (int m = 0; m < 4; ++m) {
                int kk = k4 * 4 + m;
                float4 w0 = *(const float4*)&sW[kk * 256 + tx * 4];
                float4 w1 = *(const float4*)&sW[kk * 256 + 128 + tx * 4];
                float w[8] = {w0.x, w0.y, w0.z, w0.w, w1.x, w1.y, w1.z, w1.w};
#pragma unroll
                for (int rr = 0; rr < 8; ++rr) {
                    float a = (m == 0) ? a4[rr].x : (m == 1) ? a4[rr].y
                             : (m == 2) ? a4[rr].z : a4[rr].w;
#pragma unroll
                    for (int cc = 0; cc < 8; ++cc) acc[rr][cc] += a * w[cc];
                }
            }
        }
        __syncthreads();
    }

    if (EPI == 0) {
#pragma unroll
        for (int rr = 0; rr < 8; ++rr) {
            int row = row0 + ty * 8 + rr;
#pragma unroll
            for (int cc = 0; cc < 8; ++cc) {
                int n = colmap(tx, cc);
                if (n < N) C[(size_t)row * N + n] = acc[rr][cc];
            }
        }
    } else {
        float invN = 1.f / (float)N;
#pragma unroll
        for (int rr = 0; rr < 8; ++rr) {
            int row = row0 + ty * 8 + rr;
            float v[8]; float s = 0.f;
#pragma unroll
            for (int cc = 0; cc < 8; ++cc) {
                int n = colmap(tx, cc);
                float t = 0.f;
                if (n < N) t = fmaxf(acc[rr][cc] + bias[n], 0.f);
                v[cc] = t; s += t;
            }
            s = warp_sum(s);
            float mu = s * invN;
            float q = 0.f;
#pragma unroll
            for (int cc = 0; cc < 8; ++cc) {
                int n = colmap(tx, cc);
                if (n < N) { float d = v[cc] - mu; q += d * d; }
            }
            q = warp_sum(q);
            float rs = rsqrtf(q * invN + 1e-5f);
#pragma unroll
            for (int cc = 0; cc < 8; ++cc) {
                int n = colmap(tx, cc);
                if (n < N) C[(size_t)row * N + n] = (v[cc] - mu) * rs * g[n] + bt[n];
            }
        }
    }
}

// ---------------------------------------------------------------------------
// Output GEMM: new_state = [s1 | effect | x] @ out_W + out_b.
// K = 1076, N = 250, M = 16384. Same BM=64 tile, conflict-free W reads.
// ---------------------------------------------------------------------------
__global__ __launch_bounds__(256, 2)
void out_gemm_kernel(const float* __restrict__ s1, const float* __restrict__ eff,
                     const float* __restrict__ x, const float* __restrict__ W,
                     const float* __restrict__ bias, float* __restrict__ C)
{
    const int K = 1076, N = 250;
    __shared__ float sA[64 * 20];
    __shared__ float sW[16 * 256];
    const int tid = threadIdx.x;
    const int tx = tid & 31, ty = tid >> 5;
    const int row0 = blockIdx.x * 64;

    float acc[8][8];
#pragma unroll
    for (int r = 0; r < 8; ++r)
#pragma unroll
        for (int c = 0; c < 8; ++c) acc[r][c] = 0.f;

    for (int kt = 0; kt < K; kt += 16) {
#pragma unroll
        for (int t = 0; t < 4; ++t) {
            int idx = tid + t * 256;
            int r = idx >> 4, kk = idx & 15;
            int k = kt + kk;
            int row = row0 + r;
            float av = 0.f;
            if (k < 250)       av = s1 [(size_t)row * 250 + k];
            else if (k < 500)  av = eff[(size_t)row * 250 + (k - 250)];
            else if (k < 1076) av = x  [(size_t)row * 576 + (k - 500)];
            sA[r * 20 + kk] = av;
        }
#pragma unroll
        for (int t = 0; t < 16; ++t) {
            int k = kt + t;
            sW[t * 256 + tid] = (k < K && tid < N) ? W[(size_t)k * N + tid] : 0.f;
        }
        __syncthreads();
#pragma unroll
        for (int k4 = 0; k4 < 4; ++k4) {
            float4 a4[8];
#pragma unroll
            for (int rr = 0; rr < 8; ++rr)
                a4[rr] = *(const float4*)&sA[(ty * 8 + rr) * 20 + k4 * 4];
#pragma unroll
            for (int m = 0; m < 4; ++m) {
                int kk = k4 * 4 + m;
                float4 w0 = *(const float4*)&sW[kk * 256 + tx * 4];
                float4 w1 = *(const float4*)&sW[kk * 256 + 128 + tx * 4];
                float w[8] = {w0.x, w0.y, w0.z, w0.w, w1.x, w1.y, w1.z, w1.w};
#pragma unroll
                for (int rr = 0; rr < 8; ++rr) {
                    float a = (m == 0) ? a4[rr].x : (m == 1) ? a4[rr].y
                             : (m == 2) ? a4[rr].z : a4[rr].w;
#pragma unroll
                    for (int cc = 0; cc < 8; ++cc) acc[rr][cc] += a * w[cc];
                }
            }
        }
        __syncthreads();
    }
#pragma unroll
    for (int rr = 0; rr < 8; ++rr) {
        int row = row0 + ty * 8 + rr;
#pragma unroll
        for (int cc = 0; cc < 8; ++cc) {
            int n = colmap(tx, cc);
            if (n < N) C[(size_t)row * N + n] = acc[rr][cc] + bias[n];
        }
    }
}

// ---------------------------------------------------------------------------
// Fused pair kernel: one block per b (56 pair rows).
//  core_out = LN(relu(P[i] + Q[j] + core_b))       -> SMEM 56x256 (zero-pad)
//  att      = sigmoid(LN(tanh(core@attW1+b1))@attW2+b2)
//  ctx      = LN(relu(core@ctxW + ctx_b))
//  effect[b*8+i] = sum_jj ctx[i*7+jj]*att[i*7+jj]  (in-register, no atomics)
// W reads conflict-free via colmap slabs.
// ---------------------------------------------------------------------------
#define SC_STRIDE 256
#define SM_SC   0
#define SM_UN   (56 * SC_STRIDE)        /* 14336: union region, 4096 floats */
#define SM_ATT  (SM_UN + 4096)          /* 18432 */
#define SM_TOT  (SM_ATT + 64)           /* 18496 floats = 73984 B */

__global__ __launch_bounds__(256, 2)
void pair_kernel(const float* __restrict__ P, const float* __restrict__ Q,
                 const float* __restrict__ core_b, const float* __restrict__ core_g,
                 const float* __restrict__ core_bt,
                 const float* __restrict__ ctxW, const float* __restrict__ ctx_b,
                 const float* __restrict__ ctx_g, const float* __restrict__ ctx_bt,
                 const float* __restrict__ attW1, const float* __restrict__ att_b1,
                 const float* __restrict__ att_g, const float* __restrict__ att_bt,
                 const float* __restrict__ attW2, const float* __restrict__ att_b2,
                 float* __restrict__ effect)
{
    extern __shared__ float sm[];
    float* sC   = sm + SM_SC;
    float* sP   = sm + SM_UN;            // staging (phase 1 only)
    float* sQ   = sm + SM_UN + 2016;     // 8*252
    float* sW   = sm + SM_UN;            // weight tiles (phases 2-3)
    float* sAtt = sm + SM_ATT;

    const int tid = threadIdx.x;
    const int tx = tid & 31, ty = tid >> 5;
    const int b = blockIdx.x;

    // --- phase 1: load P,Q rows, build core_out into sC ---
    for (int idx = tid; idx < 8 * 250; idx += 256) {
        int i = idx / 250, c = idx % 250;
        sP[i * 252 + c] = P[(size_t)(b * 8 + i) * 250 + c];
        sQ[i * 252 + c] = Q[(size_t)(b * 8 + i) * 250 + c];
    }
    __syncthreads();

    for (int r = ty; r < 56; r += 8) {
        int i = r / 7, jj = r % 7;
        int j = jj + (jj >= i ? 1 : 0);
        float v[8]; float s = 0.f;
#pragma unroll
        for (int t = 0; t < 8; ++t) {
            int c = tx + 32 * t;
            float val = 0.f;
            if (c < 250) val = fmaxf(sP[i * 252 + c] + sQ[j * 252 + c] + core_b[c], 0.f);
            v[t] = val; s += val;
        }
        s = warp_sum(s);
        float mu = s * (1.f / 250.f);
        float q = 0.f;
#pragma unroll
        for (int t = 0; t < 8; ++t) {
            int c = tx + 32 * t;
            if (c < 250) { float d = v[t] - mu; q += d * d; }
        }
        q = warp_sum(q);
        float rs = rsqrtf(q * (1.f / 250.f) + 1e-5f);
#pragma unroll
        for (int t = 0; t < 8; ++t) {
            int c = tx + 32 * t;
            if (c < 250) sC[r * SC_STRIDE + c] = (v[t] - mu) * rs * core_g[c] + core_bt[c];
            else         sC[r * SC_STRIDE + c] = 0.f;   // zero pad to 256
        }
    }
    __syncthreads();   // sP/sQ dead from here; sW may overwrite

    // --- phase 2: attention GEMM 56 x 100, K=250 (sW stride 128) ---
    float accA[7][4];
#pragma unroll
    for (int r = 0; r < 7; ++r)
#pragma unroll
        for (int c = 0; c < 4; ++c) accA[r][c] = 0.f;

    for (int kt = 0; kt < 250; kt += 16) {
#pragma unroll
        for (int t = 0; t < 8; ++t) {
            int idx = tid + t * 256;
            int kk = idx >> 7, n = idx & 127;
            int k = kt + kk;
            sW[kk * 128 + n] = (k < 250 && n < 100) ? attW1[(size_t)k * 100 + n] : 0.f;
        }
        __syncthreads();
#pragma unroll
        for (int k4 = 0; k4 < 4; ++k4) {
            float4 a4[7];
#pragma unroll
            for (int rr = 0; rr < 7; ++rr)
                a4[rr] = *(const float4*)&sC[(ty * 7 + rr) * SC_STRIDE + kt + k4 * 4];
#pragma unroll
            for (int m = 0; m < 4; ++m) {
                int kk = k4 * 4 + m;
                float4 w4 = *(const float4*)&sW[kk * 128 + tx * 4];   // contiguous: conflict-free
                float w[4] = {w4.x, w4.y, w4.z, w4.w};
#pragma unroll
                for (int rr = 0; rr < 7; ++rr) {
                    float a = (m == 0) ? a4[rr].x : (m == 1) ? a4[rr].y
                             : (m == 2) ? a4[rr].z : a4[rr].w;
#pragma unroll
                    for (int cc = 0; cc < 4; ++cc) accA[rr][cc] += a * w[cc];
                }
            }
        }
        __syncthreads();
    }

    // attention epilogue: tanh, LN(100), dot attW2, sigmoid
#pragma unroll
    for (int rr = 0; rr < 7; ++rr) {
        int row = ty * 7 + rr;
        float h[4]; float s = 0.f;
#pragma unroll
        for (int cc = 0; cc < 4; ++cc) {
            int c = tx * 4 + cc;
            float t = 0.f;
            if (c < 100) t = tanhf(accA[rr][cc] + att_b1[c]);
            h[cc] = t; s += t;
        }
        s = warp_sum(s);
        float mu = s * (1.f / 100.f);
        float q = 0.f;
#pragma unroll
        for (int cc = 0; cc < 4; ++cc) {
            int c = tx * 4 + cc;
            if (c < 100) { float d = h[cc] - mu; q += d * d; }
        }
        q = warp_sum(q);
        float rs = rsqrtf(q * (1.f / 100.f) + 1e-5f);
        float p = 0.f;
#pragma unroll
        for (int cc = 0; cc < 4; ++cc) {
            int c = tx * 4 + cc;
            if (c < 100) p += ((h[cc] - mu) * rs * att_g[c] + att_bt[c]) * attW2[c];
        }
        p = warp_sum(p);
        if (tx == 0) sAtt[row] = 1.f / (1.f + expf(-(p + att_b2[0])));
    }
    __syncthreads();

    // --- phase 3: ctx GEMM 56 x 250, K=250 (sW stride 256, colmap cols) ---
    float accC[7][8];
#pragma unroll
    for (int r = 0; r < 7; ++r)
#pragma unroll
        for (int c = 0; c < 8; ++c) accC[r][c] = 0.f;

    for (int kt = 0; kt < 250; kt += 16) {
#pragma unroll
        for (int t = 0; t < 16; ++t) {
            int k = kt + t;
            sW[t * 256 + tid] = (k < 250 && tid < 250) ? ctxW[(size_t)k * 250 + tid] : 0.f;
        }
        __syncthreads();
#pragma unroll
        for (int k4 = 0; k4 < 4; ++k4) {
            float4 a4[7];
#pragma unroll
            for (int rr = 0; rr < 7; ++rr)
                a4[rr] = *(const float4*)&sC[(ty * 7 + rr) * SC_STRIDE + kt + k4 * 4];
#pragma unroll
            for (int m = 0; m < 4; ++m) {
                int kk = k4 * 4 + m;
                float4 w0 = *(const float4*)&sW[kk * 256 + tx * 4];
                float4 w1 = *(const float4*)&sW[kk * 256 + 128 + tx * 4];
                float w[8] = {w0.x, w0.y, w0.z, w0.w, w1.x, w1.y, w1.z, w1.w};
#pragma unroll
                for (int rr = 0; rr < 7; ++rr) {
                    float a = (m == 0) ? a4[rr].x : (m == 1) ? a4[rr].y
                             : (m == 2) ? a4[rr].z : a4[rr].w;
#pragma unroll
                    for (int cc = 0; cc < 8; ++cc) accC[rr][cc] += a * w[cc];
                }
            }
        }
        __syncthreads();
    }

    // --- ctx epilogue + effect reduce (warp ty owns i-group ty) ---
    float eff[8];
#pragma unroll
    for (int cc = 0; cc < 8; ++cc) eff[cc] = 0.f;
#pragma unroll
    for (int rr = 0; rr < 7; ++rr) {
        int row = ty * 7 + rr;
        float v[8]; float s = 0.f;
#pragma unroll
        for (int cc = 0; cc < 8; ++cc) {
            int c = colmap(tx, cc);
            float t = 0.f;
            if (c < 250) t = fmaxf(accC[rr][cc] + ctx_b[c], 0.f);
            v[cc] = t; s += t;
        }
        s = warp_sum(s);
        float mu = s * (1.f / 250.f);
        float q = 0.f;
#pragma unroll
        for (int cc = 0; cc < 8; ++cc) {
            int c = colmap(tx, cc);
            if (c < 250) { float d = v[cc] - mu; q += d * d; }
        }
        q = warp_sum(q);
        float rs = rsqrtf(q * (1.f / 250.f) + 1e-5f);
        float aw = sAtt[row];
#pragma unroll
        for (int cc = 0; cc < 8; ++cc) {
            int c = colmap(tx, cc);
            if (c < 250) eff[cc] += ((v[cc] - mu) * rs * ctx_g[c] + ctx_bt[c]) * aw;
        }
    }
#pragma unroll
    for (int cc = 0; cc < 8; ++cc) {
        int c = colmap(tx, cc);
        if (c < 250) effect[(size_t)(b * 8 + ty) * 250 + c] = eff[cc];
    }
}

// ---------------------------------------------------------------------------
extern "C" void kernel_launch(void* const* d_in, const int* in_sizes, int n_in,
                              void* d_out, int out_size)
{
    const float* x      = (const float*)d_in[0];
    const float* state  = (const float*)d_in[1];
    const float* enc_W  = (const float*)d_in[2];
    const float* enc_b  = (const float*)d_in[3];
    const float* enc_g  = (const float*)d_in[4];
    const float* enc_bt = (const float*)d_in[5];
    const float* core_W = (const float*)d_in[6];
    const float* core_b = (const float*)d_in[7];
    const float* core_g = (const float*)d_in[8];
    const float* core_bt= (const float*)d_in[9];
    const float* ctx_W  = (const float*)d_in[10];
    const float* ctx_b  = (const float*)d_in[11];
    const float* ctx_g  = (const float*)d_in[12];
    const float* ctx_bt = (const float*)d_in[13];
    const float* att_W1 = (const float*)d_in[14];
    const float* att_b1 = (const float*)d_in[15];
    const float* att_g  = (const float*)d_in[16];
    const float* att_bt = (const float*)d_in[17];
    const float* att_W2 = (const float*)d_in[18];
    const float* att_b2 = (const float*)d_in[19];
    const float* out_W  = (const float*)d_in[20];
    const float* out_b  = (const float*)d_in[21];
    float* out = (float*)d_out;

    float *p_s1, *p_P, *p_Q, *p_eff;
    cudaGetSymbolAddress((void**)&p_s1,  g_s1);
    cudaGetSymbolAddress((void**)&p_P,   g_P);
    cudaGetSymbolAddress((void**)&p_Q,   g_Q);
    cudaGetSymbolAddress((void**)&p_eff, g_eff);

    cudaFuncSetAttribute(pair_kernel, cudaFuncAttributeMaxDynamicSharedMemorySize,
                         SM_TOT * (int)sizeof(float));

    // 1) s1 = LN(relu(state @ enc_W + enc_b))
    gemm_kernel<1><<<ROWS / 64, 256>>>(state, enc_W, enc_b, enc_g, enc_bt,
                                       p_s1, ROWS, 250, 250);
    // 2) P = s1 @ core_W[:250], Q = s1 @ core_W[250:]
    gemm_kernel<0><<<ROWS / 64, 256>>>(p_s1, core_W, nullptr, nullptr, nullptr,
                                       p_P, ROWS, 250, 250);
    gemm_kernel<0><<<ROWS / 64, 256>>>(p_s1, core_W + 250 * 250, nullptr, nullptr, nullptr,
                                       p_Q, ROWS, 250, 250);
    // 3) fused pair/ctx/att/effect
    pair_kernel<<<NB, 256, SM_TOT * (int)sizeof(float)>>>(
        p_P, p_Q, core_b, core_g, core_bt,
        ctx_W, ctx_b, ctx_g, ctx_bt,
        att_W1, att_b1, att_g, att_bt,
        att_W2, att_b2, p_eff);
    // 4) new_state = [s1|effect|x] @ out_W + out_b
    out_gemm_kernel<<<ROWS / 64, 256>>>(p_s1, p_eff, x, out_W, out_b, out);
}

// round 4
// speedup vs baseline: 1.4059x; 1.0477x over previous
#include <cuda_runtime.h>
#include <math.h>

// Problem constants
#define NB     2048            // batch groups b
#define KOBJ   8               // K objects
#define H1     250
#define ROWS   (NB*KOBJ)       // 16384

// Scratch (device globals; no allocations allowed)
__device__ float g_s1 [ROWS*H1];
__device__ float g_P  [ROWS*H1];
__device__ float g_Q  [ROWS*H1];
__device__ float g_eff[ROWS*H1];

typedef unsigned long long u64;

__device__ __forceinline__ float warp_sum(float v) {
#pragma unroll
    for (int o = 16; o; o >>= 1) v += __shfl_xor_sync(0xffffffffu, v, o);
    return v;
}

// packed f32x2 fma: d = a*b + d (elementwise on packed pairs)
__device__ __forceinline__ void ffma2(u64& d, u64 a, u64 b) {
    asm("fma.rn.f32x2 %0, %1, %2, %0;" : "+l"(d) : "l"(a), "l"(b));
}
// duplicate scalar into both halves of a packed pair
__device__ __forceinline__ u64 dup2(float x) {
    u64 r;
    asm("mov.b64 %0, {%1, %1};" : "=l"(r) : "r"(__float_as_uint(x)));
    return r;
}
// unpack packed pair
__device__ __forceinline__ float2 unpk(u64 v) {
    float2 f;
    asm("mov.b64 {%0, %1}, %2;" : "=f"(f.x), "=f"(f.y) : "l"(v));
    return f;
}
__device__ __forceinline__ float fsel(float4 v, int m) {
    return (m == 0) ? v.x : (m == 1) ? v.y : (m == 2) ? v.z : v.w;
}

// Column owned by lane tx, slot cc (pairs adjacent):
// cc 0..3 -> tx*4+cc ; cc 4..7 -> 128 + tx*4 + (cc-4)
__device__ __forceinline__ int colmap(int tx, int cc) {
    return (cc < 4) ? (tx * 4 + cc) : (128 + tx * 4 + (cc - 4));
}

// ---------------------------------------------------------------------------
// Tiled SGEMM: C = epi(A[M,K] @ W[K,N]); BM=64, BN=256(>=N), BK=16.
// FFMA2 inner loop: acc = packed col-pairs; W read as u64 pairs from the
// conflict-free float4 slab; A broadcast dup'd via mov.b64.
// EPI==0: plain store. EPI==1: +bias, relu, LayerNorm(g,bt).
// ---------------------------------------------------------------------------
template <int EPI>
__global__ __launch_bounds__(256, 2)
void gemm_kernel(const float* __restrict__ A, const float* __restrict__ W,
                 const float* __restrict__ bias, const float* __restrict__ g,
                 const float* __restrict__ bt, float* __restrict__ C,
                 int M, int K, int N)
{
    __shared__ float sA[64 * 20];
    __shared__ float sW[16 * 256];
    const int tid = threadIdx.x;
    const int tx = tid & 31, ty = tid >> 5;
    const int row0 = blockIdx.x * 64;

    u64 acc2[8][4];
#pragma unroll
    for (int r = 0; r < 8; ++r)
#pragma unroll
        for (int p = 0; p < 4; ++p) acc2[r][p] = 0ull;

    for (int kt = 0; kt < K; kt += 16) {
#pragma unroll
        for (int t = 0; t < 4; ++t) {
            int idx = tid + t * 256;
            int r = idx >> 4, kk = idx & 15;
            int k = kt + kk;
            sA[r * 20 + kk] = (k < K) ? A[(size_t)(row0 + r) * K + k] : 0.f;
        }
#pragma unroll
        for (int t = 0; t < 16; ++t) {
            int k = kt + t;
            sW[t * 256 + tid] = (k < K && tid < N) ? W[(size_t)k * N + tid] : 0.f;
        }
        __syncthreads();
#pragma unroll
        for (int k4 = 0; k4 < 4; ++k4) {
            float4 a4[8];
#pragma unroll
            for (int rr = 0; rr < 8; ++rr)
                a4[rr] = *(const float4*)&sA[(ty * 8 + rr) * 20 + k4 * 4];
#pragma unroll
            for (int m = 0; m < 4; ++m) {
                int kk = k4 * 4 + m;
                ulonglong2 wv0 = *(const ulonglong2*)&sW[kk * 256 + tx * 4];
                ulonglong2 wv1 = *(const ulonglong2*)&sW[kk * 256 + 128 + tx * 4];
                u64 w2[4] = {wv0.x, wv0.y, wv1.x, wv1.y};
#pragma unroll
                for (int rr = 0; rr < 8; ++rr) {
                    u64 ad = dup2(fsel(a4[rr], m));
#pragma unroll
                    for (int p = 0; p < 4; ++p) ffma2(acc2[rr][p], ad, w2[p]);
                }
            }
        }
        __syncthreads();
    }

    if (EPI == 0) {
#pragma unroll
        for (int rr = 0; rr < 8; ++rr) {
            int row = row0 + ty * 8 + rr;
#pragma unroll
            for (int p = 0; p < 4; ++p) {
                float2 f = unpk(acc2[rr][p]);
                int n0 = colmap(tx, 2 * p);
                if (n0 < N)     C[(size_t)row * N + n0]     = f.x;
                if (n0 + 1 < N) C[(size_t)row * N + n0 + 1] = f.y;
            }
        }
    } else {
        float invN = 1.f / (float)N;
#pragma unroll
        for (int rr = 0; rr < 8; ++rr) {
            int row = row0 + ty * 8 + rr;
            float v[8]; float s = 0.f;
#pragma unroll
            for (int cc = 0; cc < 8; ++cc) {
                float2 f = unpk(acc2[rr][cc >> 1]);
                float raw = (cc & 1) ? f.y : f.x;
                int n = colmap(tx, cc);
                float t = 0.f;
                if (n < N) t = fmaxf(raw + bias[n], 0.f);
                v[cc] = t; s += t;
            }
            s = warp_sum(s);
            float mu = s * invN;
            float q = 0.f;
#pragma unroll
            for (int cc = 0; cc < 8; ++cc) {
                int n = colmap(tx, cc);
                if (n < N) { float d = v[cc] - mu; q += d * d; }
            }
            q = warp_sum(q);
            float rs = rsqrtf(q * invN + 1e-5f);
#pragma unroll
            for (int cc = 0; cc < 8; ++cc) {
                int n = colmap(tx, cc);
                if (n < N) C[(size_t)row * N + n] = (v[cc] - mu) * rs * g[n] + bt[n];
            }
        }
    }
}

// ---------------------------------------------------------------------------
// Output GEMM: new_state = [s1 | effect | x] @ out_W + out_b.
// K = 1076, N = 250, M = 16384. FFMA2 inner loop.
// ---------------------------------------------------------------------------
__global__ __launch_bounds__(256, 2)
void out_gemm_kernel(const float* __restrict__ s1, const float* __restrict__ eff,
                     const float* __restrict__ x, const float* __restrict__ W,
                     const float* __restrict__ bias, float* __restrict__ C)
{
    const int K = 1076, N = 250;
    __shared__ float sA[64 * 20];
    __shared__ float sW[16 * 256];
    const int tid = threadIdx.x;
    const int tx = tid & 31, ty = tid >> 5;
    const int row0 = blockIdx.x * 64;

    u64 acc2[8][4];
#pragma unroll
    for (int r = 0; r < 8; ++r)
#pragma unroll
        for (int p = 0; p < 4; ++p) acc2[r][p] = 0ull;

    for (int kt = 0; kt < K; kt += 16) {
#pragma unroll
        for (int t = 0; t < 4; ++t) {
            int idx = tid + t * 256;
            int r = idx >> 4, kk = idx & 15;
            int k = kt + kk;
            int row = row0 + r;
            float av = 0.f;
            if (k < 250)       av = s1 [(size_t)row * 250 + k];
            else if (k < 500)  av = eff[(size_t)row * 250 + (k - 250)];
            else if (k < 1076) av = x  [(size_t)row * 576 + (k - 500)];
            sA[r * 20 + kk] = av;
        }
#pragma unroll
        for (int t = 0; t < 16; ++t) {
            int k = kt + t;
            sW[t * 256 + tid] = (k < K && tid < N) ? W[(size_t)k * N + tid] : 0.f;
        }
        __syncthreads();
#pragma unroll
        for (int k4 = 0; k4 < 4; ++k4) {
            float4 a4[8];
#pragma unroll
            for (int rr = 0; rr < 8; ++rr)
                a4[rr] = *(const float4*)&sA[(ty * 8 + rr) * 20 + k4 * 4];
#pragma unroll
            for (int m = 0; m < 4; ++m) {
                int kk = k4 * 4 + m;
                ulonglong2 wv0 = *(const ulonglong2*)&sW[kk * 256 + tx * 4];
                ulonglong2 wv1 = *(const ulonglong2*)&sW[kk * 256 + 128 + tx * 4];
                u64 w2[4] = {wv0.x, wv0.y, wv1.x, wv1.y};
#pragma unroll
                for (int rr = 0; rr < 8; ++rr) {
                    u64 ad = dup2(fsel(a4[rr], m));
#pragma unroll
                    for (int p = 0; p < 4; ++p) ffma2(acc2[rr][p], ad, w2[p]);
                }
            }
        }
        __syncthreads();
    }
#pragma unroll
    for (int rr = 0; rr < 8; ++rr) {
        int row = row0 + ty * 8 + rr;
#pragma unroll
        for (int p = 0; p < 4; ++p) {
            float2 f = unpk(acc2[rr][p]);
            int n0 = colmap(tx, 2 * p);
            if (n0 < N)     C[(size_t)row * N + n0]     = f.x + bias[n0];
            if (n0 + 1 < N) C[(size_t)row * N + n0 + 1] = f.y + bias[n0 + 1];
        }
    }
}

// ---------------------------------------------------------------------------
// Fused pair kernel: one block per b (56 pair rows). FFMA2 GEMM loops.
// ---------------------------------------------------------------------------
#define SC_STRIDE 256
#define SM_SC   0
#define SM_UN   (56 * SC_STRIDE)        /* 14336: union region, 4096 floats */
#define SM_ATT  (SM_UN + 4096)          /* 18432 */
#define SM_TOT  (SM_ATT + 64)           /* 18496 floats = 73984 B */

__global__ __launch_bounds__(256, 2)
void pair_kernel(const float* __restrict__ P, const float* __restrict__ Q,
                 const float* __restrict__ core_b, const float* __restrict__ core_g,
                 const float* __restrict__ core_bt,
                 const float* __restrict__ ctxW, const float* __restrict__ ctx_b,
                 const float* __restrict__ ctx_g, const float* __restrict__ ctx_bt,
                 const float* __restrict__ attW1, const float* __restrict__ att_b1,
                 const float* __restrict__ att_g, const float* __restrict__ att_bt,
                 const float* __restrict__ attW2, const float* __restrict__ att_b2,
                 float* __restrict__ effect)
{
    extern __shared__ float sm[];
    float* sC   = sm + SM_SC;
    float* sP   = sm + SM_UN;            // staging (phase 1 only)
    float* sQ   = sm + SM_UN + 2016;     // 8*252
    float* sW   = sm + SM_UN;            // weight tiles (phases 2-3)
    float* sAtt = sm + SM_ATT;

    const int tid = threadIdx.x;
    const int tx = tid & 31, ty = tid >> 5;
    const int b = blockIdx.x;

    // --- phase 1: load P,Q rows, build core_out into sC ---
    for (int idx = tid; idx < 8 * 250; idx += 256) {
        int i = idx / 250, c = idx % 250;
        sP[i * 252 + c] = P[(size_t)(b * 8 + i) * 250 + c];
        sQ[i * 252 + c] = Q[(size_t)(b * 8 + i) * 250 + c];
    }
    __syncthreads();

    for (int r = ty; r < 56; r += 8) {
        int i = r / 7, jj = r % 7;
        int j = jj + (jj >= i ? 1 : 0);
        float v[8]; float s = 0.f;
#pragma unroll
        for (int t = 0; t < 8; ++t) {
            int c = tx + 32 * t;
            float val = 0.f;
            if (c < 250) val = fmaxf(sP[i * 252 + c] + sQ[j * 252 + c] + core_b[c], 0.f);
            v[t] = val; s += val;
        }
        s = warp_sum(s);
        float mu = s * (1.f / 250.f);
        float q = 0.f;
#pragma unroll
        for (int t = 0; t < 8; ++t) {
            int c = tx + 32 * t;
            if (c < 250) { float d = v[t] - mu; q += d * d; }
        }
        q = warp_sum(q);
        float rs = rsqrtf(q * (1.f / 250.f) + 1e-5f);
#pragma unroll
        for (int t = 0; t < 8; ++t) {
            int c = tx + 32 * t;
            if (c < 250) sC[r * SC_STRIDE + c] = (v[t] - mu) * rs * core_g[c] + core_bt[c];
            else         sC[r * SC_STRIDE + c] = 0.f;   // zero pad to 256
        }
    }
    __syncthreads();   // sP/sQ dead from here; sW may overwrite

    // --- phase 2: attention GEMM 56 x 100, K=250 (sW stride 128) ---
    u64 accA2[7][2];
#pragma unroll
    for (int r = 0; r < 7; ++r)
#pragma unroll
        for (int p = 0; p < 2; ++p) accA2[r][p] = 0ull;

    for (int kt = 0; kt < 250; kt += 16) {
#pragma unroll
        for (int t = 0; t < 8; ++t) {
            int idx = tid + t * 256;
            int kk = idx >> 7, n = idx & 127;
            int k = kt + kk;
            sW[kk * 128 + n] = (k < 250 && n < 100) ? attW1[(size_t)k * 100 + n] : 0.f;
        }
        __syncthreads();
#pragma unroll
        for (int k4 = 0; k4 < 4; ++k4) {
            float4 a4[7];
#pragma unroll
            for (int rr = 0; rr < 7; ++rr)
                a4[rr] = *(const float4*)&sC[(ty * 7 + rr) * SC_STRIDE + kt + k4 * 4];
#pragma unroll
            for (int m = 0; m < 4; ++m) {
                int kk = k4 * 4 + m;
                ulonglong2 wv = *(const ulonglong2*)&sW[kk * 128 + tx * 4];
                u64 w2[2] = {wv.x, wv.y};
#pragma unroll
                for (int rr = 0; rr < 7; ++rr) {
                    u64 ad = dup2(fsel(a4[rr], m));
#pragma unroll
                    for (int p = 0; p < 2; ++p) ffma2(accA2[rr][p], ad, w2[p]);
                }
            }
        }
        __syncthreads();
    }

    // attention epilogue: tanh, LN(100), dot attW2, sigmoid
#pragma unroll
    for (int rr = 0; rr < 7; ++rr) {
        int row = ty * 7 + rr;
        float h[4]; float s = 0.f;
#pragma unroll
        for (int cc = 0; cc < 4; ++cc) {
            float2 f = unpk(accA2[rr][cc >> 1]);
            float raw = (cc & 1) ? f.y : f.x;
            int c = tx * 4 + cc;
            float t = 0.f;
            if (c < 100) t = tanhf(raw + att_b1[c]);
            h[cc] = t; s += t;
        }
        s = warp_sum(s);
        float mu = s * (1.f / 100.f);
        float q = 0.f;
#pragma unroll
        for (int cc = 0; cc < 4; ++cc) {
            int c = tx * 4 + cc;
            if (c < 100) { float d = h[cc] - mu; q += d * d; }
        }
        q = warp_sum(q);
        float rs = rsqrtf(q * (1.f / 100.f) + 1e-5f);
        float p = 0.f;
#pragma unroll
        for (int cc = 0; cc < 4; ++cc) {
            int c = tx * 4 + cc;
            if (c < 100) p += ((h[cc] - mu) * rs * att_g[c] + att_bt[c]) * attW2[c];
        }
        p = warp_sum(p);
        if (tx == 0) sAtt[row] = 1.f / (1.f + expf(-(p + att_b2[0])));
    }
    __syncthreads();

    // --- phase 3: ctx GEMM 56 x 250, K=250 (sW stride 256) ---
    u64 accC2[7][4];
#pragma unroll
    for (int r = 0; r < 7; ++r)
#pragma unroll
        for (int p = 0; p < 4; ++p) accC2[r][p] = 0ull;

    for (int kt = 0; kt < 250; kt += 16) {
#pragma unroll
        for (int t = 0; t < 16; ++t) {
            int k = kt + t;
            sW[t * 256 + tid] = (k < 250 && tid < 250) ? ctxW[(size_t)k * 250 + tid] : 0.f;
        }
        __syncthreads();
#pragma unroll
        for (int k4 = 0; k4 < 4; ++k4) {
            float4 a4[7];
#pragma unroll
            for (int rr = 0; rr < 7; ++rr)
                a4[rr] = *(const float4*)&sC[(ty * 7 + rr) * SC_STRIDE + kt + k4 * 4];
#pragma unroll
            for (int m = 0; m < 4; ++m) {
                int kk = k4 * 4 + m;
                ulonglong2 wv0 = *(const ulonglong2*)&sW[kk * 256 + tx * 4];
                ulonglong2 wv1 = *(const ulonglong2*)&sW[kk * 256 + 128 + tx * 4];
                u64 w2[4] = {wv0.x, wv0.y, wv1.x, wv1.y};
#pragma unroll
                for (int rr = 0; rr < 7; ++rr) {
                    u64 ad = dup2(fsel(a4[rr], m));
#pragma unroll
                    for (int p = 0; p < 4; ++p) ffma2(accC2[rr][p], ad, w2[p]);
                }
            }
        }
        __syncthreads();
    }

    // --- ctx epilogue + effect reduce (warp ty owns i-group ty) ---
    float eff[8];
#pragma unroll
    for (int cc = 0; cc < 8; ++cc) eff[cc] = 0.f;
#pragma unroll
    for (int rr = 0; rr < 7; ++rr) {
        int row = ty * 7 + rr;
        float v[8]; float s = 0.f;
#pragma unroll
        for (int cc = 0; cc < 8; ++cc) {
            float2 f = unpk(accC2[rr][cc >> 1]);
            float raw = (cc & 1) ? f.y : f.x;
            int c = colmap(tx, cc);
            float t = 0.f;
            if (c < 250) t = fmaxf(raw + ctx_b[c], 0.f);
            v[cc] = t; s += t;
        }
        s = warp_sum(s);
        float mu = s * (1.f / 250.f);
        float q = 0.f;
#pragma unroll
        for (int cc = 0; cc < 8; ++cc) {
            int c = colmap(tx, cc);
            if (c < 250) { float d = v[cc] - mu; q += d * d; }
        }
        q = warp_sum(q);
        float rs = rsqrtf(q * (1.f / 250.f) + 1e-5f);
        float aw = sAtt[row];
#pragma unroll
        for (int cc = 0; cc < 8; ++cc) {
            int c = colmap(tx, cc);
            if (c < 250) eff[cc] += ((v[cc] - mu) * rs * ctx_g[c] + ctx_bt[c]) * aw;
        }
    }
#pragma unroll
    for (int cc = 0; cc < 8; ++cc) {
        int c = colmap(tx, cc);
        if (c < 250) effect[(size_t)(b * 8 + ty) * 250 + c] = eff[cc];
    }
}

// ---------------------------------------------------------------------------
extern "C" void kernel_launch(void* const* d_in, const int* in_sizes, int n_in,
                              void* d_out, int out_size)
{
    const float* x      = (const float*)d_in[0];
    const float* state  = (const float*)d_in[1];
    const float* enc_W  = (const float*)d_in[2];
    const float* enc_b  = (const float*)d_in[3];
    const float* enc_g  = (const float*)d_in[4];
    const float* enc_bt = (const float*)d_in[5];
    const float* core_W = (const float*)d_in[6];
    const float* core_b = (const float*)d_in[7];
    const float* core_g = (const float*)d_in[8];
    const float* core_bt= (const float*)d_in[9];
    const float* ctx_W  = (const float*)d_in[10];
    const float* ctx_b  = (const float*)d_in[11];
    const float* ctx_g  = (const float*)d_in[12];
    const float* ctx_bt = (const float*)d_in[13];
    const float* att_W1 = (const float*)d_in[14];
    const float* att_b1 = (const float*)d_in[15];
    const float* att_g  = (const float*)d_in[16];
    const float* att_bt = (const float*)d_in[17];
    const float* att_W2 = (const float*)d_in[18];
    const float* att_b2 = (const float*)d_in[19];
    const float* out_W  = (const float*)d_in[20];
    const float* out_b  = (const float*)d_in[21];
    float* out = (float*)d_out;

    float *p_s1, *p_P, *p_Q, *p_eff;
    cudaGetSymbolAddress((void**)&p_s1,  g_s1);
    cudaGetSymbolAddress((void**)&p_P,   g_P);
    cudaGetSymbolAddress((void**)&p_Q,   g_Q);
    cudaGetSymbolAddress((void**)&p_eff, g_eff);

    cudaFuncSetAttribute(pair_kernel, cudaFuncAttributeMaxDynamicSharedMemorySize,
                         SM_TOT * (int)sizeof(float));

    // 1) s1 = LN(relu(state @ enc_W + enc_b))
    gemm_kernel<1><<<ROWS / 64, 256>>>(state, enc_W, enc_b, enc_g, enc_bt,
                                       p_s1, ROWS, 250, 250);
    // 2) P = s1 @ core_W[:250], Q = s1 @ core_W[250:]
    gemm_kernel<0><<<ROWS / 64, 256>>>(p_s1, core_W, nullptr, nullptr, nullptr,
                                       p_P, ROWS, 250, 250);
    gemm_kernel<0><<<ROWS / 64, 256>>>(p_s1, core_W + 250 * 250, nullptr, nullptr, nullptr,
                                       p_Q, ROWS, 250, 250);
    // 3) fused pair/ctx/att/effect
    pair_kernel<<<NB, 256, SM_TOT * (int)sizeof(float)>>>(
        p_P, p_Q, core_b, core_g, core_bt,
        ctx_W, ctx_b, ctx_g, ctx_bt,
        att_W1, att_b1, att_g, att_bt,
        att_W2, att_b2, p_eff);
    // 4) new_state = [s1|effect|x] @ out_W + out_b
    out_gemm_kernel<<<ROWS / 64, 256>>>(p_s1, p_eff, x, out_W, out_b, out);
}

// round 5
// speedup vs baseline: 1.4096x; 1.0026x over previous
#include <cuda_runtime.h>
#include <math.h>

#define NB     2048
#define KOBJ   8
#define H1     250
#define ROWS   (NB*KOBJ)       // 16384

__device__ float g_s1 [ROWS*H1];
__device__ float g_P  [ROWS*H1];
__device__ float g_Q  [ROWS*H1];
__device__ float g_eff[ROWS*H1];

typedef unsigned long long u64;

__device__ __forceinline__ float warp_sum(float v) {
#pragma unroll
    for (int o = 16; o; o >>= 1) v += __shfl_xor_sync(0xffffffffu, v, o);
    return v;
}

// packed f32x2 fma: d = a*b + d
__device__ __forceinline__ void ffma2(u64& d, u64 a, u64 b) {
    asm("fma.rn.f32x2 %0, %1, %2, %0;" : "+l"(d) : "l"(a), "l"(b));
}
__device__ __forceinline__ u64 dup2(float x) {
    u64 r;
    asm("mov.b64 %0, {%1, %1};" : "=l"(r) : "r"(__float_as_uint(x)));
    return r;
}
__device__ __forceinline__ float2 unpk(u64 v) {
    float2 f;
    asm("mov.b64 {%0, %1}, %2;" : "=f"(f.x), "=f"(f.y) : "l"(v));
    return f;
}
__device__ __forceinline__ float fsel(float4 v, int m) {
    return (m == 0) ? v.x : (m == 1) ? v.y : (m == 2) ? v.z : v.w;
}

// cp.async helpers (LDGSTS): zero-register global->shared copies
__device__ __forceinline__ void cp8(void* s, const void* g) {
    asm volatile("cp.async.ca.shared.global [%0], [%1], 8;"
                 :: "r"((unsigned)__cvta_generic_to_shared(s)), "l"(g));
}
__device__ __forceinline__ void cp4(void* s, const void* g) {
    asm volatile("cp.async.ca.shared.global [%0], [%1], 4;"
                 :: "r"((unsigned)__cvta_generic_to_shared(s)), "l"(g));
}
#define CP_COMMIT() asm volatile("cp.async.commit_group;")
#define CP_WAIT1()  asm volatile("cp.async.wait_group 1;")

// Column owned by lane tx, slot cc (pairs adjacent)
__device__ __forceinline__ int colmap(int tx, int cc) {
    return (cc < 4) ? (tx * 4 + cc) : (128 + tx * 4 + (cc - 4));
}

// ---------------------------------------------------------------------------
// Tiled SGEMM with double-buffered cp.async pipeline.
// C = epi(A[M,K] @ W[K,N]); BM=64, BN=256(>=N), BK=16; 256 threads.
// ---------------------------------------------------------------------------
template <int EPI>
__global__ __launch_bounds__(256, 2)
void gemm_kernel(const float* __restrict__ A, const float* __restrict__ W,
                 const float* __restrict__ bias, const float* __restrict__ g,
                 const float* __restrict__ bt, float* __restrict__ C,
                 int M, int K, int N)
{
    __shared__ float sA[2][64 * 20];
    __shared__ float sW[2][16 * 256];
    const int tid = threadIdx.x;
    const int tx = tid & 31, ty = tid >> 5;
    const int row0 = blockIdx.x * 64;
    const int NT = (K + 15) >> 4;

    auto issue = [&](int t, int buf) {
        int kt = t * 16;
        // A tile: 64x16, 8B chunks (2 per thread)
#pragma unroll
        for (int c = 0; c < 2; ++c) {
            int q = tid + c * 256;
            int r = q >> 3, kk0 = (q & 7) * 2;
            int k = kt + kk0;
            float* d = &sA[buf][r * 20 + kk0];
            if (k + 2 <= K)     cp8(d, &A[(size_t)(row0 + r) * K + k]);
            else if (k < K) { cp4(d, &A[(size_t)(row0 + r) * K + k]); d[1] = 0.f; }
            else *(float2*)d = make_float2(0.f, 0.f);
        }
        // W tile: 16x256, 8B chunks (8 per thread)
#pragma unroll
        for (int c = 0; c < 8; ++c) {
            int q = tid + c * 256;
            int kk = q >> 7, n0 = (q & 127) * 2;
            int k = kt + kk;
            float* d = &sW[buf][kk * 256 + n0];
            if (k < K && n0 + 2 <= N)   cp8(d, &W[(size_t)k * N + n0]);
            else if (k < K && n0 < N) { cp4(d, &W[(size_t)k * N + n0]); d[1] = 0.f; }
            else *(float2*)d = make_float2(0.f, 0.f);
        }
    };

    u64 acc2[8][4];
#pragma unroll
    for (int r = 0; r < 8; ++r)
#pragma unroll
        for (int p = 0; p < 4; ++p) acc2[r][p] = 0ull;

    issue(0, 0); CP_COMMIT();
    for (int t = 0; t < NT; ++t) {
        if (t + 1 < NT) issue(t + 1, (t + 1) & 1);
        CP_COMMIT();
        CP_WAIT1();
        __syncthreads();
        const float* aT = sA[t & 1];
        const float* wT = sW[t & 1];
#pragma unroll
        for (int k4 = 0; k4 < 4; ++k4) {
            float4 a4[8];
#pragma unroll
            for (int rr = 0; rr < 8; ++rr)
                a4[rr] = *(const float4*)&aT[(ty * 8 + rr) * 20 + k4 * 4];
#pragma unroll
            for (int m = 0; m < 4; ++m) {
                int kk = k4 * 4 + m;
                ulonglong2 wv0 = *(const ulonglong2*)&wT[kk * 256 + tx * 4];
                ulonglong2 wv1 = *(const ulonglong2*)&wT[kk * 256 + 128 + tx * 4];
                u64 w2[4] = {wv0.x, wv0.y, wv1.x, wv1.y};
#pragma unroll
                for (int rr = 0; rr < 8; ++rr) {
                    u64 ad = dup2(fsel(a4[rr], m));
#pragma unroll
                    for (int p = 0; p < 4; ++p) ffma2(acc2[rr][p], ad, w2[p]);
                }
            }
        }
        __syncthreads();
    }

    if (EPI == 0) {
#pragma unroll
        for (int rr = 0; rr < 8; ++rr) {
            int row = row0 + ty * 8 + rr;
#pragma unroll
            for (int p = 0; p < 4; ++p) {
                float2 f = unpk(acc2[rr][p]);
                int n0 = colmap(tx, 2 * p);
                if (n0 < N)     C[(size_t)row * N + n0]     = f.x;
                if (n0 + 1 < N) C[(size_t)row * N + n0 + 1] = f.y;
            }
        }
    } else {
        float invN = 1.f / (float)N;
#pragma unroll
        for (int rr = 0; rr < 8; ++rr) {
            int row = row0 + ty * 8 + rr;
            float v[8]; float s = 0.f;
#pragma unroll
            for (int cc = 0; cc < 8; ++cc) {
                float2 f = unpk(acc2[rr][cc >> 1]);
                float raw = (cc & 1) ? f.y : f.x;
                int n = colmap(tx, cc);
                float t = 0.f;
                if (n < N) t = fmaxf(raw + bias[n], 0.f);
                v[cc] = t; s += t;
            }
            s = warp_sum(s);
            float mu = s * invN;
            float q = 0.f;
#pragma unroll
            for (int cc = 0; cc < 8; ++cc) {
                int n = colmap(tx, cc);
                if (n < N) { float d = v[cc] - mu; q += d * d; }
            }
            q = warp_sum(q);
            float rs = rsqrtf(q * invN + 1e-5f);
#pragma unroll
            for (int cc = 0; cc < 8; ++cc) {
                int n = colmap(tx, cc);
                if (n < N) C[(size_t)row * N + n] = (v[cc] - mu) * rs * g[n] + bt[n];
            }
        }
    }
}

// ---------------------------------------------------------------------------
// Output GEMM: new_state = [s1 | effect | x] @ out_W + out_b. K=1076, N=250.
// ---------------------------------------------------------------------------
__global__ __launch_bounds__(256, 2)
void out_gemm_kernel(const float* __restrict__ s1, const float* __restrict__ eff,
                     const float* __restrict__ x, const float* __restrict__ W,
                     const float* __restrict__ bias, float* __restrict__ C)
{
    const int K = 1076, N = 250;
    __shared__ float sA[2][64 * 20];
    __shared__ float sW[2][16 * 256];
    const int tid = threadIdx.x;
    const int tx = tid & 31, ty = tid >> 5;
    const int row0 = blockIdx.x * 64;
    const int NT = (K + 15) >> 4;   // 68

    auto issue = [&](int t, int buf) {
        int kt = t * 16;
        // A tile: gathered from 3 sources, 4B cp.async per element
#pragma unroll
        for (int c = 0; c < 4; ++c) {
            int q = tid + c * 256;
            int r = q >> 4, kk = q & 15;
            int k = kt + kk;
            int row = row0 + r;
            float* d = &sA[buf][r * 20 + kk];
            if (k < 250)       cp4(d, &s1 [(size_t)row * 250 + k]);
            else if (k < 500)  cp4(d, &eff[(size_t)row * 250 + (k - 250)]);
            else if (k < 1076) cp4(d, &x  [(size_t)row * 576 + (k - 500)]);
            else *d = 0.f;
        }
#pragma unroll
        for (int c = 0; c < 8; ++c) {
            int q = tid + c * 256;
            int kk = q >> 7, n0 = (q & 127) * 2;
            int k = kt + kk;
            float* d = &sW[buf][kk * 256 + n0];
            if (k < K && n0 + 2 <= N)   cp8(d, &W[(size_t)k * N + n0]);
            else if (k < K && n0 < N) { cp4(d, &W[(size_t)k * N + n0]); d[1] = 0.f; }
            else *(float2*)d = make_float2(0.f, 0.f);
        }
    };

    u64 acc2[8][4];
#pragma unroll
    for (int r = 0; r < 8; ++r)
#pragma unroll
        for (int p = 0; p < 4; ++p) acc2[r][p] = 0ull;

    issue(0, 0); CP_COMMIT();
    for (int t = 0; t < NT; ++t) {
        if (t + 1 < NT) issue(t + 1, (t + 1) & 1);
        CP_COMMIT();
        CP_WAIT1();
        __syncthreads();
        const float* aT = sA[t & 1];
        const float* wT = sW[t & 1];
#pragma unroll
        for (int k4 = 0; k4 < 4; ++k4) {
            float4 a4[8];
#pragma unroll
            for (int rr = 0; rr < 8; ++rr)
                a4[rr] = *(const float4*)&aT[(ty * 8 + rr) * 20 + k4 * 4];
#pragma unroll
            for (int m = 0; m < 4; ++m) {
                int kk = k4 * 4 + m;
                ulonglong2 wv0 = *(const ulonglong2*)&wT[kk * 256 + tx * 4];
                ulonglong2 wv1 = *(const ulonglong2*)&wT[kk * 256 + 128 + tx * 4];
                u64 w2[4] = {wv0.x, wv0.y, wv1.x, wv1.y};
#pragma unroll
                for (int rr = 0; rr < 8; ++rr) {
                    u64 ad = dup2(fsel(a4[rr], m));
#pragma unroll
                    for (int p = 0; p < 4; ++p) ffma2(acc2[rr][p], ad, w2[p]);
                }
            }
        }
        __syncthreads();
    }
#pragma unroll
    for (int rr = 0; rr < 8; ++rr) {
        int row = row0 + ty * 8 + rr;
#pragma unroll
        for (int p = 0; p < 4; ++p) {
            float2 f = unpk(acc2[rr][p]);
            int n0 = colmap(tx, 2 * p);
            if (n0 < N)     C[(size_t)row * N + n0]     = f.x + bias[n0];
            if (n0 + 1 < N) C[(size_t)row * N + n0 + 1] = f.y + bias[n0 + 1];
        }
    }
}

// ---------------------------------------------------------------------------
// Fused pair kernel (one block per b): double-buffered cp.async W tiles.
// SMEM: sC 56x256 | union { sP/sQ staging , 2x tile buffers (8192 fl) } | sAtt
// ---------------------------------------------------------------------------
#define SC_STRIDE 256
#define SM_SC   0
#define SM_UN   (56 * SC_STRIDE)        /* 14336; union region 8192 floats */
#define SM_ATT  (SM_UN + 8192)          /* 22528 */
#define SM_TOT  (SM_ATT + 64)           /* 22592 floats = 90368 B */

__global__ __launch_bounds__(256, 2)
void pair_kernel(const float* __restrict__ P, const float* __restrict__ Q,
                 const float* __restrict__ core_b, const float* __restrict__ core_g,
                 const float* __restrict__ core_bt,
                 const float* __restrict__ ctxW, const float* __restrict__ ctx_b,
                 const float* __restrict__ ctx_g, const float* __restrict__ ctx_bt,
                 const float* __restrict__ attW1, const float* __restrict__ att_b1,
                 const float* __restrict__ att_g, const float* __restrict__ att_bt,
                 const float* __restrict__ attW2, const float* __restrict__ att_b2,
                 float* __restrict__ effect)
{
    extern __shared__ float sm[];
    float* sC   = sm + SM_SC;
    float* sP   = sm + SM_UN;            // staging (phase 1 only)
    float* sQ   = sm + SM_UN + 2016;
    float* sW   = sm + SM_UN;            // tile buffers (phases 2-3)
    float* sAtt = sm + SM_ATT;

    const int tid = threadIdx.x;
    const int tx = tid & 31, ty = tid >> 5;
    const int b = blockIdx.x;

    // att tile: 16x128 at sW + buf*2048 ; ctx tile: 16x256 at sW + buf*4096
    auto issue_att = [&](int t, int buf) {
        int kt = t * 16;
#pragma unroll
        for (int c = 0; c < 4; ++c) {
            int q = tid + c * 256;
            int kk = q >> 6, n0 = (q & 63) * 2;
            int k = kt + kk;
            float* d = &sW[buf * 2048 + kk * 128 + n0];
            if (k < 250 && n0 + 2 <= 100) cp8(d, &attW1[(size_t)k * 100 + n0]);
            else *(float2*)d = make_float2(0.f, 0.f);
        }
    };
    auto issue_ctx = [&](int t, int buf) {
        int kt = t * 16;
#pragma unroll
        for (int c = 0; c < 8; ++c) {
            int q = tid + c * 256;
            int kk = q >> 7, n0 = (q & 127) * 2;
            int k = kt + kk;
            float* d = &sW[buf * 4096 + kk * 256 + n0];
            if (k < 250 && n0 + 2 <= 250) cp8(d, &ctxW[(size_t)k * 250 + n0]);
            else *(float2*)d = make_float2(0.f, 0.f);
        }
    };

    // --- phase 1: load P,Q rows, build core_out into sC ---
    for (int idx = tid; idx < 8 * 250; idx += 256) {
        int i = idx / 250, c = idx % 250;
        sP[i * 252 + c] = P[(size_t)(b * 8 + i) * 250 + c];
        sQ[i * 252 + c] = Q[(size_t)(b * 8 + i) * 250 + c];
    }
    __syncthreads();

    for (int r = ty; r < 56; r += 8) {
        int i = r / 7, jj = r % 7;
        int j = jj + (jj >= i ? 1 : 0);
        float v[8]; float s = 0.f;
#pragma unroll
        for (int t = 0; t < 8; ++t) {
            int c = tx + 32 * t;
            float val = 0.f;
            if (c < 250) val = fmaxf(sP[i * 252 + c] + sQ[j * 252 + c] + core_b[c], 0.f);
            v[t] = val; s += val;
        }
        s = warp_sum(s);
        float mu = s * (1.f / 250.f);
        float q = 0.f;
#pragma unroll
        for (int t = 0; t < 8; ++t) {
            int c = tx + 32 * t;
            if (c < 250) { float d = v[t] - mu; q += d * d; }
        }
        q = warp_sum(q);
        float rs = rsqrtf(q * (1.f / 250.f) + 1e-5f);
#pragma unroll
        for (int t = 0; t < 8; ++t) {
            int c = tx + 32 * t;
            if (c < 250) sC[r * SC_STRIDE + c] = (v[t] - mu) * rs * core_g[c] + core_bt[c];
            else         sC[r * SC_STRIDE + c] = 0.f;
        }
    }
    __syncthreads();   // sP/sQ dead; tile buffers live from here

    // --- phase 2: attention GEMM 56 x 100, K=250, pipelined ---
    u64 accA2[7][2];
#pragma unroll
    for (int r = 0; r < 7; ++r)
#pragma unroll
        for (int p = 0; p < 2; ++p) accA2[r][p] = 0ull;

    issue_att(0, 0); CP_COMMIT();
    for (int t = 0; t < 16; ++t) {
        if (t + 1 < 16) issue_att(t + 1, (t + 1) & 1);
        CP_COMMIT();
        CP_WAIT1();
        __syncthreads();
        const float* wT = sW + (t & 1) * 2048;
        int kt = t * 16;
#pragma unroll
        for (int k4 = 0; k4 < 4; ++k4) {
            float4 a4[7];
#pragma unroll
            for (int rr = 0; rr < 7; ++rr)
                a4[rr] = *(const float4*)&sC[(ty * 7 + rr) * SC_STRIDE + kt + k4 * 4];
#pragma unroll
            for (int m = 0; m < 4; ++m) {
                int kk = k4 * 4 + m;
                ulonglong2 wv = *(const ulonglong2*)&wT[kk * 128 + tx * 4];
                u64 w2[2] = {wv.x, wv.y};
#pragma unroll
                for (int rr = 0; rr < 7; ++rr) {
                    u64 ad = dup2(fsel(a4[rr], m));
#pragma unroll
                    for (int p = 0; p < 2; ++p) ffma2(accA2[rr][p], ad, w2[p]);
                }
            }
        }
        __syncthreads();
    }

    // prefetch ctx tile 0 (buffers free: att loop fully done) before epilogue math
    issue_ctx(0, 0); CP_COMMIT();

    // attention epilogue: tanh, LN(100), dot attW2, sigmoid
#pragma unroll
    for (int rr = 0; rr < 7; ++rr) {
        int row = ty * 7 + rr;
        float h[4]; float s = 0.f;
#pragma unroll
        for (int cc = 0; cc < 4; ++cc) {
            float2 f = unpk(accA2[rr][cc >> 1]);
            float raw = (cc & 1) ? f.y : f.x;
            int c = tx * 4 + cc;
            float t = 0.f;
            if (c < 100) t = tanhf(raw + att_b1[c]);
            h[cc] = t; s += t;
        }
        s = warp_sum(s);
        float mu = s * (1.f / 100.f);
        float q = 0.f;
#pragma unroll
        for (int cc = 0; cc < 4; ++cc) {
            int c = tx * 4 + cc;
            if (c < 100) { float d = h[cc] - mu; q += d * d; }
        }
        q = warp_sum(q);
        float rs = rsqrtf(q * (1.f / 100.f) + 1e-5f);
        float p = 0.f;
#pragma unroll
        for (int cc = 0; cc < 4; ++cc) {
            int c = tx * 4 + cc;
            if (c < 100) p += ((h[cc] - mu) * rs * att_g[c] + att_bt[c]) * attW2[c];
        }
        p = warp_sum(p);
        if (tx == 0) sAtt[row] = 1.f / (1.f + expf(-(p + att_b2[0])));
    }
    __syncthreads();

    // --- phase 3: ctx GEMM 56 x 250, K=250, pipelined ---
    u64 accC2[7][4];
#pragma unroll
    for (int r = 0; r < 7; ++r)
#pragma unroll
        for (int p = 0; p < 4; ++p) accC2[r][p] = 0ull;

    for (int t = 0; t < 16; ++t) {
        if (t + 1 < 16) issue_ctx(t + 1, (t + 1) & 1);
        CP_COMMIT();
        CP_WAIT1();
        __syncthreads();
        const float* wT = sW + (t & 1) * 4096;
        int kt = t * 16;
#pragma unroll
        for (int k4 = 0; k4 < 4; ++k4) {
            float4 a4[7];
#pragma unroll
            for (int rr = 0; rr < 7; ++rr)
                a4[rr] = *(const float4*)&sC[(ty * 7 + rr) * SC_STRIDE + kt + k4 * 4];
#pragma unroll
            for (int m = 0; m < 4; ++m) {
                int kk = k4 * 4 + m;
                ulonglong2 wv0 = *(const ulonglong2*)&wT[kk * 256 + tx * 4];
                ulonglong2 wv1 = *(const ulonglong2*)&wT[kk * 256 + 128 + tx * 4];
                u64 w2[4] = {wv0.x, wv0.y, wv1.x, wv1.y};
#pragma unroll
                for (int rr = 0; rr < 7; ++rr) {
                    u64 ad = dup2(fsel(a4[rr], m));
#pragma unroll
                    for (int p = 0; p < 4; ++p) ffma2(accC2[rr][p], ad, w2[p]);
                }
            }
        }
        __syncthreads();
    }

    // --- ctx epilogue + effect reduce (warp ty owns i-group ty) ---
    float eff[8];
#pragma unroll
    for (int cc = 0; cc < 8; ++cc) eff[cc] = 0.f;
#pragma unroll
    for (int rr = 0; rr < 7; ++rr) {
        int row = ty * 7 + rr;
        float v[8]; float s = 0.f;
#pragma unroll
        for (int cc = 0; cc < 8; ++cc) {
            float2 f = unpk(accC2[rr][cc >> 1]);
            float raw = (cc & 1) ? f.y : f.x;
            int c = colmap(tx, cc);
            float t = 0.f;
            if (c < 250) t = fmaxf(raw + ctx_b[c], 0.f);
            v[cc] = t; s += t;
        }
        s = warp_sum(s);
        float mu = s * (1.f / 250.f);
        float q = 0.f;
#pragma unroll
        for (int cc = 0; cc < 8; ++cc) {
            int c = colmap(tx, cc);
            if (c < 250) { float d = v[cc] - mu; q += d * d; }
        }
        q = warp_sum(q);
        float rs = rsqrtf(q * (1.f / 250.f) + 1e-5f);
        float aw = sAtt[row];
#pragma unroll
        for (int cc = 0; cc < 8; ++cc) {
            int c = colmap(tx, cc);
            if (c < 250) eff[cc] += ((v[cc] - mu) * rs * ctx_g[c] + ctx_bt[c]) * aw;
        }
    }
#pragma unroll
    for (int cc = 0; cc < 8; ++cc) {
        int c = colmap(tx, cc);
        if (c < 250) effect[(size_t)(b * 8 + ty) * 250 + c] = eff[cc];
    }
}

// ---------------------------------------------------------------------------
extern "C" void kernel_launch(void* const* d_in, const int* in_sizes, int n_in,
                              void* d_out, int out_size)
{
    const float* x      = (const float*)d_in[0];
    const float* state  = (const float*)d_in[1];
    const float* enc_W  = (const float*)d_in[2];
    const float* enc_b  = (const float*)d_in[3];
    const float* enc_g  = (const float*)d_in[4];
    const float* enc_bt = (const float*)d_in[5];
    const float* core_W = (const float*)d_in[6];
    const float* core_b = (const float*)d_in[7];
    const float* core_g = (const float*)d_in[8];
    const float* core_bt= (const float*)d_in[9];
    const float* ctx_W  = (const float*)d_in[10];
    const float* ctx_b  = (const float*)d_in[11];
    const float* ctx_g  = (const float*)d_in[12];
    const float* ctx_bt = (const float*)d_in[13];
    const float* att_W1 = (const float*)d_in[14];
    const float* att_b1 = (const float*)d_in[15];
    const float* att_g  = (const float*)d_in[16];
    const float* att_bt = (const float*)d_in[17];
    const float* att_W2 = (const float*)d_in[18];
    const float* att_b2 = (const float*)d_in[19];
    const float* out_W  = (const float*)d_in[20];
    const float* out_b  = (const float*)d_in[21];
    float* out = (float*)d_out;

    float *p_s1, *p_P, *p_Q, *p_eff;
    cudaGetSymbolAddress((void**)&p_s1,  g_s1);
    cudaGetSymbolAddress((void**)&p_P,   g_P);
    cudaGetSymbolAddress((void**)&p_Q,   g_Q);
    cudaGetSymbolAddress((void**)&p_eff, g_eff);

    cudaFuncSetAttribute(pair_kernel, cudaFuncAttributeMaxDynamicSharedMemorySize,
                         SM_TOT * (int)sizeof(float));

    gemm_kernel<1><<<ROWS / 64, 256>>>(state, enc_W, enc_b, enc_g, enc_bt,
                                       p_s1, ROWS, 250, 250);
    gemm_kernel<0><<<ROWS / 64, 256>>>(p_s1, core_W, nullptr, nullptr, nullptr,
                                       p_P, ROWS, 250, 250);
    gemm_kernel<0><<<ROWS / 64, 256>>>(p_s1, core_W + 250 * 250, nullptr, nullptr, nullptr,
                                       p_Q, ROWS, 250, 250);
    pair_kernel<<<NB, 256, SM_TOT * (int)sizeof(float)>>>(
        p_P, p_Q, core_b, core_g, core_bt,
        ctx_W, ctx_b, ctx_g, ctx_bt,
        att_W1, att_b1, att_g, att_bt,
        att_W2, att_b2, p_eff);
    out_gemm_kernel<<<ROWS / 64, 256>>>(p_s1, p_eff, x, out_W, out_b, out);
}